// round 9
// baseline (speedup 1.0000x reference)
#include <cuda_runtime.h>
#include <cuda_bf16.h>
#include <cstdint>

// Problem constants
#define A_N   100000
#define B_N   200000
#define M_N   20000
#define HDIM  256
#define MAXNB 10
#define NMOLS 2000
#define AFD   35
#define KI    40    // fbonds @ W_i
#define KO    291   // [fatoms, nei] @ W_o_w

// Scratch (device globals)
__device__ float g_binput[(size_t)B_N * HDIM];
__device__ float g_msg   [(size_t)B_N * HDIM];
__device__ float g_counts[NMOLS];
// Split bf16 operand buffers
__device__ __nv_bfloat16 g_neihi[(size_t)B_N * HDIM];
__device__ __nv_bfloat16 g_neilo[(size_t)B_N * HDIM];
__device__ __nv_bfloat16 g_fbhi [(size_t)B_N * 64];
__device__ __nv_bfloat16 g_fblo [(size_t)B_N * 64];
__device__ __nv_bfloat16 g_fahi [(size_t)A_N * 64];
__device__ __nv_bfloat16 g_falo [(size_t)A_N * 64];
// Pre-transposed, bf16-split weights: [N=256, KPAD<=320]
__device__ __nv_bfloat16 g_WThi[256 * 320];
__device__ __nv_bfloat16 g_WTlo[256 * 320];

// ---------------------------------------------------------------------------
// Helpers (base-sm_103-legal: ldmatrix / mma.sync / cp.async)
// ---------------------------------------------------------------------------
__device__ __forceinline__ uint32_t smem_u32(const void* p) {
    uint32_t a;
    asm("{ .reg .u64 t; cvta.to.shared.u64 t, %1; cvt.u32.u64 %0, t; }" : "=r"(a) : "l"(p));
    return a;
}
__device__ __forceinline__ void ldsm4(uint32_t* r, uint32_t addr) {
    asm volatile("ldmatrix.sync.aligned.m8n8.x4.shared.b16 {%0,%1,%2,%3}, [%4];"
                 : "=r"(r[0]), "=r"(r[1]), "=r"(r[2]), "=r"(r[3]) : "r"(addr));
}
__device__ __forceinline__ void mma_bf16(float* c, const uint32_t* a, uint32_t b0, uint32_t b1) {
    asm volatile("mma.sync.aligned.m16n8k16.row.col.f32.bf16.bf16.f32 "
                 "{%0,%1,%2,%3},{%4,%5,%6,%7},{%8,%9},{%0,%1,%2,%3};"
                 : "+f"(c[0]), "+f"(c[1]), "+f"(c[2]), "+f"(c[3])
                 : "r"(a[0]), "r"(a[1]), "r"(a[2]), "r"(a[3]), "r"(b0), "r"(b1));
}
__device__ __forceinline__ void cp_async16(uint32_t dst, const void* src) {
    asm volatile("cp.async.cg.shared.global [%0], [%1], 16;" :: "r"(dst), "l"(src));
}
__device__ __forceinline__ void cp_commit() {
    asm volatile("cp.async.commit_group;" ::: "memory");
}
template <int N>
__device__ __forceinline__ void cp_wait_group() {
    asm volatile("cp.async.wait_group %0;" :: "n"(N) : "memory");
}

#define SW128(o) ((o) ^ ((((uint32_t)(o)) >> 3) & 0x70))

__device__ __forceinline__ void split2(float v, unsigned short& h, unsigned short& l) {
    __nv_bfloat16 hb = __float2bfloat16_rn(v);
    float rem = v - __bfloat162float(hb);
    h = __bfloat16_as_ushort(hb);
    l = __bfloat16_as_ushort(__float2bfloat16_rn(rem));
}

// ---------------------------------------------------------------------------
// Gather + sum over MAX_NB neighbor rows of virtual concat [tree ; msg],
// emitting bf16 hi/lo split of the fp32 sum. RELU=1: apply relu to msg-branch
// rows on the fly (msg buffer then holds PRE-activation values, e.g. binput).
// ---------------------------------------------------------------------------
template <int RELU>
__global__ void gather_split_kernel(const int* __restrict__ graph, int rows,
                                    const float* __restrict__ tree,
                                    const float* __restrict__ msg,
                                    __nv_bfloat16* __restrict__ outhi,
                                    __nv_bfloat16* __restrict__ outlo)
{
    int row = blockIdx.x * blockDim.y + threadIdx.y;
    if (row >= rows) return;
    int t = threadIdx.x;  // 0..63
    const int* gr = graph + (size_t)row * MAXNB;
    float4 acc = make_float4(0.f, 0.f, 0.f, 0.f);
#pragma unroll
    for (int j = 0; j < MAXNB; j++) {
        int idx = __ldg(&gr[j]);
        bool isMsg = (idx >= M_N);
        const float* srcp = isMsg ? (msg + (size_t)(idx - M_N) * HDIM)
                                  : (tree + (size_t)idx * HDIM);
        float4 v = __ldg(((const float4*)srcp) + t);
        if (RELU && isMsg) {
            v.x = fmaxf(v.x, 0.f); v.y = fmaxf(v.y, 0.f);
            v.z = fmaxf(v.z, 0.f); v.w = fmaxf(v.w, 0.f);
        }
        acc.x += v.x; acc.y += v.y; acc.z += v.z; acc.w += v.w;
    }
    unsigned short h0,h1,h2,h3,l0,l1,l2,l3;
    split2(acc.x,h0,l0); split2(acc.y,h1,l1); split2(acc.z,h2,l2); split2(acc.w,h3,l3);
    uint2 uh, ul;
    uh.x = (uint32_t)h0 | ((uint32_t)h1 << 16);
    uh.y = (uint32_t)h2 | ((uint32_t)h3 << 16);
    ul.x = (uint32_t)l0 | ((uint32_t)l1 << 16);
    ul.y = (uint32_t)l2 | ((uint32_t)l3 << 16);
    ((uint2*)outhi)[(size_t)row * 64 + t] = uh;
    ((uint2*)outlo)[(size_t)row * 64 + t] = ul;
}

// ---------------------------------------------------------------------------
// Prep: fp32 [rows, inK] -> bf16 hi/lo [rows, 64] zero-padded
// ---------------------------------------------------------------------------
__global__ void prep_a_kernel(const float* __restrict__ in, int rows, int inK,
                              __nv_bfloat16* __restrict__ hi, __nv_bfloat16* __restrict__ lo)
{
    size_t i = (size_t)blockIdx.x * blockDim.x + threadIdx.x;
    if (i >= (size_t)rows * 64) return;
    int r = (int)(i >> 6), k = (int)(i & 63);
    float v = (k < inK) ? __ldg(&in[(size_t)r * inK + k]) : 0.f;
    unsigned short h, l; split2(v, h, l);
    hi[i] = __ushort_as_bfloat16(h);
    lo[i] = __ushort_as_bfloat16(l);
}

// ---------------------------------------------------------------------------
// Weight prep: W [Kdim, 256] fp32 -> WT hi/lo bf16 [256, Kpad] (zero padded).
// ROT=1: source row = (k + AFD) % Kdim -> [nei | fatoms] ordering.
// ---------------------------------------------------------------------------
template <int ROT>
__global__ void prep_w_kernel(const float* __restrict__ W, int Kdim, int Kpad,
                              __nv_bfloat16* __restrict__ hi, __nv_bfloat16* __restrict__ lo)
{
    int i = blockIdx.x * blockDim.x + threadIdx.x;
    if (i >= 256 * Kpad) return;
    int n = i / Kpad, k = i % Kpad;
    float v = 0.f;
    if (k < Kdim) {
        int src = ROT ? (k + AFD) % Kdim : k;
        v = __ldg(&W[(size_t)src * 256 + n]);
    }
    unsigned short h, l; split2(v, h, l);
    hi[i] = __ushort_as_bfloat16(h);
    lo[i] = __ushort_as_bfloat16(l);
}

// ---------------------------------------------------------------------------
// Pure bf16 3-split HGEMM, fully double-buffered: 128x256 CTA tile,
// 512 threads (16 warps, 2(M)x8(N) grid, 64x32 warp tiles). A and B both
// via cp.async into double buffers (A 2x32KB, B 2x64KB = 192KB smem,
// 1 CTA/SM). Zero exposed load latency: (A,B)(s+1) committed before
// waiting on (s).
// MODE 0: out1 = C (binput only; relu applied later in gather)
// MODE 1: out1 = relu(binput + C) (msg)
// MODE 2: relu(C + bias) atomicAdd into out1[scope[row]]; stage NS-1 A
//         comes from (A2hi,A2lo,strideA2) [fatoms], earlier from nei.
// ---------------------------------------------------------------------------
#define TILE_M   128
#define ABUF(s)  ((uint32_t)((s) & 1) * 32768)
#define A_LO_OFF 16384
#define BBUF(s)  (65536 + (uint32_t)((s) & 1) * 65536)
#define B_LO_OFF 32768
#define HG_SMEM  196608

template <int MODE, int NS>
__global__ __launch_bounds__(512, 1)
void hgemm_kernel(const __nv_bfloat16* __restrict__ Ahi,
                  const __nv_bfloat16* __restrict__ Alo,
                  int strideA,
                  const __nv_bfloat16* __restrict__ A2hi,
                  const __nv_bfloat16* __restrict__ A2lo,
                  int strideA2,
                  const __nv_bfloat16* __restrict__ WThi,
                  const __nv_bfloat16* __restrict__ WTlo,
                  int rowsM,
                  const float* __restrict__ binput,
                  const float* __restrict__ bias,
                  const int*   __restrict__ scope,
                  float* __restrict__ out1)
{
    constexpr int KPAD = NS * 64;
    extern __shared__ char smem[];
    const uint32_t sb = smem_u32(smem);
    const int tid  = threadIdx.x;
    const int lane = tid & 31, wid = tid >> 5;
    const int wm = wid & 1, wn = wid >> 1;     // 2 x 8 warp grid
    const int rowBlock = blockIdx.x * TILE_M;

    // ldmatrix lane-address components
    const int arow  = ((lane >> 3) & 1) * 8 + (lane & 7);
    const int akb   = (lane >> 4) * 16;
    const int bnrow = ((lane >> 4) & 1) * 8 + (lane & 7);
    const int bkb   = ((lane >> 3) & 1) * 16;

    float acc[4][4][4];   // [mi][ni(8cols)][quad]
#pragma unroll
    for (int mi = 0; mi < 4; mi++)
#pragma unroll
        for (int ni = 0; ni < 4; ni++)
#pragma unroll
            for (int e = 0; e < 4; e++) acc[mi][ni][e] = 0.f;

    auto cpA = [&](int s) {   // 128 rows x 64 cols bf16 (hi+lo), SW128
        const __nv_bfloat16 *sh, *sl;
        int stride, kk0;
        if (MODE == 2 && s == NS - 1) { sh = A2hi; sl = A2lo; stride = strideA2; kk0 = 0; }
        else                          { sh = Ahi;  sl = Alo;  stride = strideA;  kk0 = s * 64; }
        uint32_t abuf = ABUF(s);
#pragma unroll
        for (int i = 0; i < 2; i++) {
            int idx = i * 512 + tid;          // 1024 16B-chunks per half
            int r = idx >> 3, c = idx & 7;
            int grow = rowBlock + r;
            if (grow >= rowsM) grow = rowsM - 1;   // clamp; epilogue guards stores
            uint32_t dsw = SW128(r * 128 + c * 16);
            size_t src = (size_t)grow * stride + kk0 + c * 8;
            cp_async16(sb + abuf + dsw,            sh + src);
            cp_async16(sb + abuf + A_LO_OFF + dsw, sl + src);
        }
    };

    auto cpB = [&](int s) {   // 256 n-rows x 64 k-cols bf16 (hi+lo), SW128
        int k0 = s * 64;
        uint32_t bbuf = BBUF(s);
#pragma unroll
        for (int i = 0; i < 4; i++) {
            int idx = i * 512 + tid;          // 2048 16B-chunks per half
            int n = idx >> 3, c = idx & 7;
            uint32_t dsw = SW128(n * 128 + c * 16);
            size_t src = (size_t)n * KPAD + k0 + c * 8;
            cp_async16(sb + bbuf + dsw,            WThi + src);
            cp_async16(sb + bbuf + B_LO_OFF + dsw, WTlo + src);
        }
    };

    // Prologue: stage 0 in flight
    cpA(0); cpB(0); cp_commit();

    for (int s = 0; s < NS; s++) {
        if (s + 1 < NS) {
            cpA(s + 1); cpB(s + 1); cp_commit();
            cp_wait_group<1>();     // stage s resident; s+1 still flying
        } else {
            cp_wait_group<0>();
        }
        __syncthreads();            // stage-s tiles visible to all warps

        const uint32_t aBase = sb + ABUF(s);
        const uint32_t bBase = sb + BBUF(s);
#pragma unroll
        for (int kk = 0; kk < 4; kk++) {
#pragma unroll
            for (int nb = 0; nb < 2; nb++) {
                uint32_t boff = (uint32_t)(wn * 32 + nb * 16 + bnrow) * 128 + kk * 32 + bkb;
                uint32_t bsw = SW128(boff);
                uint32_t bh[4], bl[4];
                ldsm4(bh, bBase + bsw);
                ldsm4(bl, bBase + B_LO_OFF + bsw);
#pragma unroll
                for (int mi = 0; mi < 4; mi++) {
                    uint32_t aoff = (uint32_t)(wm * 64 + mi * 16 + arow) * 128 + kk * 32 + akb;
                    uint32_t asw = SW128(aoff);
                    uint32_t ahi[4], alo[4];
                    ldsm4(ahi, aBase + asw);
                    ldsm4(alo, aBase + A_LO_OFF + asw);
                    mma_bf16(acc[mi][2*nb],   ahi, bh[0], bh[1]);
                    mma_bf16(acc[mi][2*nb+1], ahi, bh[2], bh[3]);
                    mma_bf16(acc[mi][2*nb],   alo, bh[0], bh[1]);
                    mma_bf16(acc[mi][2*nb+1], alo, bh[2], bh[3]);
                    mma_bf16(acc[mi][2*nb],   ahi, bl[0], bl[1]);
                    mma_bf16(acc[mi][2*nb+1], ahi, bl[2], bl[3]);
                }
            }
        }
        __syncthreads();            // all warps done with stage-s buffers
    }

    // ---- Epilogue ----
#pragma unroll
    for (int mi = 0; mi < 4; mi++) {
        int r0 = rowBlock + wm * 64 + mi * 16 + (lane >> 2);
        int r1 = r0 + 8;
        int seg0 = 0, seg1 = 0;
        if (MODE == 2) {
            seg0 = (r0 < rowsM) ? __ldg(&scope[r0]) : 0;
            seg1 = (r1 < rowsM) ? __ldg(&scope[r1]) : 0;
        }
#pragma unroll
        for (int ni = 0; ni < 4; ni++) {
            int col = wn * 32 + ni * 8 + (lane & 3) * 2;
            float* c = acc[mi][ni];
            if (MODE == 0) {
                if (r0 < rowsM)
                    *(float2*)(out1 + (size_t)r0 * HDIM + col) = make_float2(c[0], c[1]);
                if (r1 < rowsM)
                    *(float2*)(out1 + (size_t)r1 * HDIM + col) = make_float2(c[2], c[3]);
            } else if (MODE == 1) {
                if (r0 < rowsM) {
                    size_t p = (size_t)r0 * HDIM + col;
                    float2 b = *(const float2*)(binput + p);
                    *(float2*)(out1 + p) = make_float2(fmaxf(c[0]+b.x,0.f), fmaxf(c[1]+b.y,0.f));
                }
                if (r1 < rowsM) {
                    size_t p = (size_t)r1 * HDIM + col;
                    float2 b = *(const float2*)(binput + p);
                    *(float2*)(out1 + p) = make_float2(fmaxf(c[2]+b.x,0.f), fmaxf(c[3]+b.y,0.f));
                }
            } else {
                float b0 = __ldg(&bias[col]), b1 = __ldg(&bias[col + 1]);
                if (r0 < rowsM) {
                    atomicAdd(&out1[(size_t)seg0 * HDIM + col],     fmaxf(c[0] + b0, 0.f));
                    atomicAdd(&out1[(size_t)seg0 * HDIM + col + 1], fmaxf(c[1] + b1, 0.f));
                }
                if (r1 < rowsM) {
                    atomicAdd(&out1[(size_t)seg1 * HDIM + col],     fmaxf(c[2] + b0, 0.f));
                    atomicAdd(&out1[(size_t)seg1 * HDIM + col + 1], fmaxf(c[3] + b1, 0.f));
                }
            }
        }
    }
}

// ---------------------------------------------------------------------------
// Pooling helpers
// ---------------------------------------------------------------------------
__global__ void zero_out_kernel(float* __restrict__ out)
{
    int i = blockIdx.x * blockDim.x + threadIdx.x;
    if (i < NMOLS * HDIM) out[i] = 0.f;
    if (i < NMOLS) g_counts[i] = 0.f;
}
__global__ void count_kernel(const int* __restrict__ scope)
{
    int i = blockIdx.x * blockDim.x + threadIdx.x;
    if (i < A_N) atomicAdd(&g_counts[__ldg(&scope[i])], 1.f);
}
__global__ void finalize_kernel(float* __restrict__ out)
{
    int i = blockIdx.x * blockDim.x + threadIdx.x;
    if (i >= NMOLS * HDIM) return;
    out[i] = out[i] / fmaxf(g_counts[i / HDIM], 1.f);
}

// ---------------------------------------------------------------------------
extern "C" void kernel_launch(void* const* d_in, const int* in_sizes, int n_in,
                              void* d_out, int out_size)
{
    const float* fatoms   = (const float*)d_in[0];
    const float* fbonds   = (const float*)d_in[1];
    const int*   agraph   = (const int*)  d_in[2];
    const int*   bgraph   = (const int*)  d_in[3];
    const float* tree_msg = (const float*)d_in[4];
    const int*   scope    = (const int*)  d_in[5];
    const float* W_i      = (const float*)d_in[6];
    const float* W_h      = (const float*)d_in[7];
    const float* W_o_w    = (const float*)d_in[8];
    const float* W_o_b    = (const float*)d_in[9];
    float* out = (float*)d_out;

    float *binput, *msg;
    __nv_bfloat16 *neihi, *neilo, *fbhi, *fblo, *fahi, *falo, *wthi, *wtlo;
    cudaGetSymbolAddress((void**)&binput, g_binput);
    cudaGetSymbolAddress((void**)&msg,    g_msg);
    cudaGetSymbolAddress((void**)&neihi,  g_neihi);
    cudaGetSymbolAddress((void**)&neilo,  g_neilo);
    cudaGetSymbolAddress((void**)&fbhi,   g_fbhi);
    cudaGetSymbolAddress((void**)&fblo,   g_fblo);
    cudaGetSymbolAddress((void**)&fahi,   g_fahi);
    cudaGetSymbolAddress((void**)&falo,   g_falo);
    cudaGetSymbolAddress((void**)&wthi,   g_WThi);
    cudaGetSymbolAddress((void**)&wtlo,   g_WTlo);

    cudaFuncSetAttribute(hgemm_kernel<0, 1>, cudaFuncAttributeMaxDynamicSharedMemorySize, HG_SMEM);
    cudaFuncSetAttribute(hgemm_kernel<1, 4>, cudaFuncAttributeMaxDynamicSharedMemorySize, HG_SMEM);
    cudaFuncSetAttribute(hgemm_kernel<2, 5>, cudaFuncAttributeMaxDynamicSharedMemorySize, HG_SMEM);

    const int gridB = (B_N + TILE_M - 1) / TILE_M;   // 1563
    const int gridA = (A_N + TILE_M - 1) / TILE_M;   // 782
    dim3 gblk(64, 4);

    // 1) prep fbonds split + W_i ; binput = fbonds @ W_i (pre-activation only)
    prep_a_kernel<<<(int)(((size_t)B_N * 64 + 255) / 256), 256>>>(fbonds, B_N, KI, fbhi, fblo);
    prep_w_kernel<0><<<(256 * 64 + 255) / 256, 256>>>(W_i, KI, 64, wthi, wtlo);
    hgemm_kernel<0, 1><<<gridB, 512, HG_SMEM>>>(
        fbhi, fblo, 64, nullptr, nullptr, 0, wthi, wtlo, B_N,
        nullptr, nullptr, nullptr, binput);

    // 2) two message-passing iterations; iter 1 gathers relu(binput) on the fly
    prep_w_kernel<0><<<(256 * 256 + 255) / 256, 256>>>(W_h, HDIM, 256, wthi, wtlo);
    gather_split_kernel<1><<<(B_N + 3) / 4, gblk>>>(bgraph, B_N, tree_msg, binput, neihi, neilo);
    hgemm_kernel<1, 4><<<gridB, 512, HG_SMEM>>>(
        neihi, neilo, HDIM, nullptr, nullptr, 0, wthi, wtlo, B_N,
        binput, nullptr, nullptr, msg);
    gather_split_kernel<0><<<(B_N + 3) / 4, gblk>>>(bgraph, B_N, tree_msg, msg, neihi, neilo);
    hgemm_kernel<1, 4><<<gridB, 512, HG_SMEM>>>(
        neihi, neilo, HDIM, nullptr, nullptr, 0, wthi, wtlo, B_N,
        binput, nullptr, nullptr, msg);

    // 3) atom gather + pooling prep + output GEMM (fused atomic segment-sum)
    gather_split_kernel<0><<<(A_N + 3) / 4, gblk>>>(agraph, A_N, tree_msg, msg, neihi, neilo);
    zero_out_kernel<<<(NMOLS * HDIM + 255) / 256, 256>>>(out);
    count_kernel<<<(A_N + 255) / 256, 256>>>(scope);
    prep_a_kernel<<<(int)(((size_t)A_N * 64 + 255) / 256), 256>>>(fatoms, A_N, AFD, fahi, falo);
    prep_w_kernel<1><<<(256 * 320 + 255) / 256, 256>>>(W_o_w, KO, 320, wthi, wtlo);
    hgemm_kernel<2, 5><<<gridA, 512, HG_SMEM>>>(
        neihi, neilo, HDIM, fahi, falo, 64, wthi, wtlo, A_N,
        nullptr, W_o_b, scope, out);
    finalize_kernel<<<(NMOLS * HDIM + 255) / 256, 256>>>(out);
}

// round 10
// speedup vs baseline: 1.0285x; 1.0285x over previous
#include <cuda_runtime.h>
#include <cuda_bf16.h>
#include <cstdint>

// Problem constants
#define A_N   100000
#define B_N   200000
#define M_N   20000
#define HDIM  256
#define MAXNB 10
#define NMOLS 2000
#define AFD   35
#define KI    40    // fbonds @ W_i
#define KO    291   // [fatoms, nei] @ W_o_w

// Scratch (device globals)
__device__ float g_binput[(size_t)B_N * HDIM];
__device__ float g_msg   [(size_t)B_N * HDIM];
__device__ float g_counts[NMOLS];
// Split bf16 operand buffers
__device__ __nv_bfloat16 g_neihi[(size_t)B_N * HDIM];
__device__ __nv_bfloat16 g_neilo[(size_t)B_N * HDIM];
__device__ __nv_bfloat16 g_fbhi [(size_t)B_N * 64];
__device__ __nv_bfloat16 g_fblo [(size_t)B_N * 64];
__device__ __nv_bfloat16 g_fahi [(size_t)A_N * 64];
__device__ __nv_bfloat16 g_falo [(size_t)A_N * 64];
// Pre-transposed, bf16-split weights: [N=256, KPAD<=320]
__device__ __nv_bfloat16 g_WThi[256 * 320];
__device__ __nv_bfloat16 g_WTlo[256 * 320];

// ---------------------------------------------------------------------------
// Helpers (base-sm_103-legal: ldmatrix / mma.sync / cp.async)
// ---------------------------------------------------------------------------
__device__ __forceinline__ uint32_t smem_u32(const void* p) {
    uint32_t a;
    asm("{ .reg .u64 t; cvta.to.shared.u64 t, %1; cvt.u32.u64 %0, t; }" : "=r"(a) : "l"(p));
    return a;
}
__device__ __forceinline__ void ldsm4(uint32_t* r, uint32_t addr) {
    asm volatile("ldmatrix.sync.aligned.m8n8.x4.shared.b16 {%0,%1,%2,%3}, [%4];"
                 : "=r"(r[0]), "=r"(r[1]), "=r"(r[2]), "=r"(r[3]) : "r"(addr));
}
__device__ __forceinline__ void mma_bf16(float* c, const uint32_t* a, uint32_t b0, uint32_t b1) {
    asm volatile("mma.sync.aligned.m16n8k16.row.col.f32.bf16.bf16.f32 "
                 "{%0,%1,%2,%3},{%4,%5,%6,%7},{%8,%9},{%0,%1,%2,%3};"
                 : "+f"(c[0]), "+f"(c[1]), "+f"(c[2]), "+f"(c[3])
                 : "r"(a[0]), "r"(a[1]), "r"(a[2]), "r"(a[3]), "r"(b0), "r"(b1));
}
__device__ __forceinline__ void cp_async16(uint32_t dst, const void* src) {
    asm volatile("cp.async.cg.shared.global [%0], [%1], 16;" :: "r"(dst), "l"(src));
}
__device__ __forceinline__ void cp_commit() {
    asm volatile("cp.async.commit_group;" ::: "memory");
}
template <int N>
__device__ __forceinline__ void cp_wait_group() {
    asm volatile("cp.async.wait_group %0;" :: "n"(N) : "memory");
}

// SW64 swizzle for 64-byte rows (conflict-free for ldmatrix + cp.async)
#define SW64(o) ((o) ^ ((((uint32_t)(o)) >> 3) & 0x30))

__device__ __forceinline__ void split2(float v, unsigned short& h, unsigned short& l) {
    __nv_bfloat16 hb = __float2bfloat16_rn(v);
    float rem = v - __bfloat162float(hb);
    h = __bfloat16_as_ushort(hb);
    l = __bfloat16_as_ushort(__float2bfloat16_rn(rem));
}

// ---------------------------------------------------------------------------
// Gather + sum over MAX_NB neighbor rows of virtual concat [tree ; msg],
// emitting bf16 hi/lo split of the fp32 sum. RELU=1: apply relu to msg-branch
// rows on the fly (msg buffer then holds PRE-activation values, e.g. binput).
// ---------------------------------------------------------------------------
template <int RELU>
__global__ void gather_split_kernel(const int* __restrict__ graph, int rows,
                                    const float* __restrict__ tree,
                                    const float* __restrict__ msg,
                                    __nv_bfloat16* __restrict__ outhi,
                                    __nv_bfloat16* __restrict__ outlo)
{
    int row = blockIdx.x * blockDim.y + threadIdx.y;
    if (row >= rows) return;
    int t = threadIdx.x;  // 0..63
    const int* gr = graph + (size_t)row * MAXNB;
    float4 acc = make_float4(0.f, 0.f, 0.f, 0.f);
#pragma unroll
    for (int j = 0; j < MAXNB; j++) {
        int idx = __ldg(&gr[j]);
        bool isMsg = (idx >= M_N);
        const float* srcp = isMsg ? (msg + (size_t)(idx - M_N) * HDIM)
                                  : (tree + (size_t)idx * HDIM);
        float4 v = __ldg(((const float4*)srcp) + t);
        if (RELU && isMsg) {
            v.x = fmaxf(v.x, 0.f); v.y = fmaxf(v.y, 0.f);
            v.z = fmaxf(v.z, 0.f); v.w = fmaxf(v.w, 0.f);
        }
        acc.x += v.x; acc.y += v.y; acc.z += v.z; acc.w += v.w;
    }
    unsigned short h0,h1,h2,h3,l0,l1,l2,l3;
    split2(acc.x,h0,l0); split2(acc.y,h1,l1); split2(acc.z,h2,l2); split2(acc.w,h3,l3);
    uint2 uh, ul;
    uh.x = (uint32_t)h0 | ((uint32_t)h1 << 16);
    uh.y = (uint32_t)h2 | ((uint32_t)h3 << 16);
    ul.x = (uint32_t)l0 | ((uint32_t)l1 << 16);
    ul.y = (uint32_t)l2 | ((uint32_t)l3 << 16);
    ((uint2*)outhi)[(size_t)row * 64 + t] = uh;
    ((uint2*)outlo)[(size_t)row * 64 + t] = ul;
}

// ---------------------------------------------------------------------------
// Prep: fp32 [rows, inK] -> bf16 hi/lo [rows, 64] zero-padded
// ---------------------------------------------------------------------------
__global__ void prep_a_kernel(const float* __restrict__ in, int rows, int inK,
                              __nv_bfloat16* __restrict__ hi, __nv_bfloat16* __restrict__ lo)
{
    size_t i = (size_t)blockIdx.x * blockDim.x + threadIdx.x;
    if (i >= (size_t)rows * 64) return;
    int r = (int)(i >> 6), k = (int)(i & 63);
    float v = (k < inK) ? __ldg(&in[(size_t)r * inK + k]) : 0.f;
    unsigned short h, l; split2(v, h, l);
    hi[i] = __ushort_as_bfloat16(h);
    lo[i] = __ushort_as_bfloat16(l);
}

// ---------------------------------------------------------------------------
// Weight prep: W [Kdim, 256] fp32 -> WT hi/lo bf16 [256, Kpad] (zero padded).
// ROT=1: source row = (k + AFD) % Kdim -> [nei | fatoms] ordering.
// ---------------------------------------------------------------------------
template <int ROT>
__global__ void prep_w_kernel(const float* __restrict__ W, int Kdim, int Kpad,
                              __nv_bfloat16* __restrict__ hi, __nv_bfloat16* __restrict__ lo)
{
    int i = blockIdx.x * blockDim.x + threadIdx.x;
    if (i >= 256 * Kpad) return;
    int n = i / Kpad, k = i % Kpad;
    float v = 0.f;
    if (k < Kdim) {
        int src = ROT ? (k + AFD) % Kdim : k;
        v = __ldg(&W[(size_t)src * 256 + n]);
    }
    unsigned short h, l; split2(v, h, l);
    hi[i] = __ushort_as_bfloat16(h);
    lo[i] = __ushort_as_bfloat16(l);
}

// ---------------------------------------------------------------------------
// Pure bf16 3-split HGEMM: 64x256 CTA tile, 256 threads (8 warps, 1x8 grid,
// 64x32 warp tiles). K-stage = 32 with BOTH operands double-buffered:
// A 2x8KB + B 2x32KB = 80KB smem -> 2 CTAs/SM AND zero exposed load latency.
// 64-byte smem rows with SW64 swizzle.
// MODE 0: out1 = C (binput; relu applied later in gather)
// MODE 1: out1 = relu(binput + C) (msg)
// MODE 2: relu(C + bias) atomicAdd into out1[scope[row]]; stages >= NS-2
//         source A from (A2hi,A2lo,strideA2) [fatoms], earlier from nei.
// ---------------------------------------------------------------------------
#define TILE_M   64
#define ABUF(s)  ((uint32_t)((s) & 1) * 8192)
#define A_LO_OFF 4096
#define BBUF(s)  (16384 + (uint32_t)((s) & 1) * 32768)
#define B_LO_OFF 16384
#define HG_SMEM  81920

template <int MODE, int NS>
__global__ __launch_bounds__(256, 2)
void hgemm_kernel(const __nv_bfloat16* __restrict__ Ahi,
                  const __nv_bfloat16* __restrict__ Alo,
                  int strideA,
                  const __nv_bfloat16* __restrict__ A2hi,
                  const __nv_bfloat16* __restrict__ A2lo,
                  int strideA2,
                  const __nv_bfloat16* __restrict__ WThi,
                  const __nv_bfloat16* __restrict__ WTlo,
                  int rowsM,
                  const float* __restrict__ binput,
                  const float* __restrict__ bias,
                  const int*   __restrict__ scope,
                  float* __restrict__ out1)
{
    constexpr int KPAD = NS * 32;
    extern __shared__ char smem[];
    const uint32_t sb = smem_u32(smem);
    const int tid  = threadIdx.x;
    const int lane = tid & 31;
    const int wn   = tid >> 5;                 // 1 x 8 warp grid
    const int rowBlock = blockIdx.x * TILE_M;

    // ldmatrix lane-address components (64B rows)
    const int arow  = ((lane >> 3) & 1) * 8 + (lane & 7);   // A row within 16
    const int akb   = (lane >> 4) * 16;                     // A col byte {0,16}
    const int bnrow = ((lane >> 4) & 1) * 8 + (lane & 7);   // B n-row within 16
    const int bkb   = ((lane >> 3) & 1) * 16;               // B col byte {0,16}

    float acc[4][4][4];   // [mi][ni(8cols)][quad]
#pragma unroll
    for (int mi = 0; mi < 4; mi++)
#pragma unroll
        for (int ni = 0; ni < 4; ni++)
#pragma unroll
            for (int e = 0; e < 4; e++) acc[mi][ni][e] = 0.f;

    auto cpA = [&](int s) {   // 64 rows x 32 K bf16 (hi+lo), SW64, 64B rows
        const __nv_bfloat16 *sh, *sl;
        int stride, kk0;
        if (MODE == 2 && s >= NS - 2) { sh = A2hi; sl = A2lo; stride = strideA2; kk0 = (s - (NS - 2)) * 32; }
        else                          { sh = Ahi;  sl = Alo;  stride = strideA;  kk0 = s * 32; }
        uint32_t abuf = ABUF(s);
        int r = tid >> 2, c = tid & 3;         // 256 threads = 64 rows x 4 chunks
        int grow = rowBlock + r;
        if (grow >= rowsM) grow = rowsM - 1;   // clamp; epilogue guards stores
        uint32_t dsw = SW64(r * 64 + c * 16);
        size_t src = (size_t)grow * stride + kk0 + c * 8;
        cp_async16(sb + abuf + dsw,            sh + src);
        cp_async16(sb + abuf + A_LO_OFF + dsw, sl + src);
    };

    auto cpB = [&](int s) {   // 256 n-rows x 32 K bf16 (hi+lo), SW64
        int k0 = s * 32;
        uint32_t bbuf = BBUF(s);
#pragma unroll
        for (int i = 0; i < 4; i++) {
            int idx = i * 256 + tid;           // 1024 16B-chunks per half
            int n = idx >> 2, c = idx & 3;
            uint32_t dsw = SW64(n * 64 + c * 16);
            size_t src = (size_t)n * KPAD + k0 + c * 8;
            cp_async16(sb + bbuf + dsw,            WThi + src);
            cp_async16(sb + bbuf + B_LO_OFF + dsw, WTlo + src);
        }
    };

    // Prologue: stage 0 in flight
    cpA(0); cpB(0); cp_commit();

    for (int s = 0; s < NS; s++) {
        if (s + 1 < NS) {
            cpA(s + 1); cpB(s + 1); cp_commit();
            cp_wait_group<1>();     // stage s resident; s+1 still flying
        } else {
            cp_wait_group<0>();
        }
        __syncthreads();            // stage-s tiles visible

        const uint32_t aBase = sb + ABUF(s);
        const uint32_t bBase = sb + BBUF(s);
#pragma unroll
        for (int kk = 0; kk < 2; kk++) {       // 2 x K16 per stage
#pragma unroll
            for (int nb = 0; nb < 2; nb++) {
                uint32_t boff = (uint32_t)(wn * 32 + nb * 16 + bnrow) * 64 + kk * 32 + bkb;
                uint32_t bsw = SW64(boff);
                uint32_t bh[4], bl[4];
                ldsm4(bh, bBase + bsw);
                ldsm4(bl, bBase + B_LO_OFF + bsw);
#pragma unroll
                for (int mi = 0; mi < 4; mi++) {
                    uint32_t aoff = (uint32_t)(mi * 16 + arow) * 64 + kk * 32 + akb;
                    uint32_t asw = SW64(aoff);
                    uint32_t ahi[4], alo[4];
                    ldsm4(ahi, aBase + asw);
                    ldsm4(alo, aBase + A_LO_OFF + asw);
                    mma_bf16(acc[mi][2*nb],   ahi, bh[0], bh[1]);
                    mma_bf16(acc[mi][2*nb+1], ahi, bh[2], bh[3]);
                    mma_bf16(acc[mi][2*nb],   alo, bh[0], bh[1]);
                    mma_bf16(acc[mi][2*nb+1], alo, bh[2], bh[3]);
                    mma_bf16(acc[mi][2*nb],   ahi, bl[0], bl[1]);
                    mma_bf16(acc[mi][2*nb+1], ahi, bl[2], bl[3]);
                }
            }
        }
        __syncthreads();            // stage-s buffers free for s+2 prefetch
    }

    // ---- Epilogue ----
#pragma unroll
    for (int mi = 0; mi < 4; mi++) {
        int r0 = rowBlock + mi * 16 + (lane >> 2);
        int r1 = r0 + 8;
        int seg0 = 0, seg1 = 0;
        if (MODE == 2) {
            seg0 = (r0 < rowsM) ? __ldg(&scope[r0]) : 0;
            seg1 = (r1 < rowsM) ? __ldg(&scope[r1]) : 0;
        }
#pragma unroll
        for (int ni = 0; ni < 4; ni++) {
            int col = wn * 32 + ni * 8 + (lane & 3) * 2;
            float* c = acc[mi][ni];
            if (MODE == 0) {
                if (r0 < rowsM)
                    *(float2*)(out1 + (size_t)r0 * HDIM + col) = make_float2(c[0], c[1]);
                if (r1 < rowsM)
                    *(float2*)(out1 + (size_t)r1 * HDIM + col) = make_float2(c[2], c[3]);
            } else if (MODE == 1) {
                if (r0 < rowsM) {
                    size_t p = (size_t)r0 * HDIM + col;
                    float2 b = *(const float2*)(binput + p);
                    *(float2*)(out1 + p) = make_float2(fmaxf(c[0]+b.x,0.f), fmaxf(c[1]+b.y,0.f));
                }
                if (r1 < rowsM) {
                    size_t p = (size_t)r1 * HDIM + col;
                    float2 b = *(const float2*)(binput + p);
                    *(float2*)(out1 + p) = make_float2(fmaxf(c[2]+b.x,0.f), fmaxf(c[3]+b.y,0.f));
                }
            } else {
                float b0 = __ldg(&bias[col]), b1 = __ldg(&bias[col + 1]);
                if (r0 < rowsM) {
                    atomicAdd(&out1[(size_t)seg0 * HDIM + col],     fmaxf(c[0] + b0, 0.f));
                    atomicAdd(&out1[(size_t)seg0 * HDIM + col + 1], fmaxf(c[1] + b1, 0.f));
                }
                if (r1 < rowsM) {
                    atomicAdd(&out1[(size_t)seg1 * HDIM + col],     fmaxf(c[2] + b0, 0.f));
                    atomicAdd(&out1[(size_t)seg1 * HDIM + col + 1], fmaxf(c[3] + b1, 0.f));
                }
            }
        }
    }
}

// ---------------------------------------------------------------------------
// Pooling helpers
// ---------------------------------------------------------------------------
__global__ void zero_out_kernel(float* __restrict__ out)
{
    int i = blockIdx.x * blockDim.x + threadIdx.x;
    if (i < NMOLS * HDIM) out[i] = 0.f;
    if (i < NMOLS) g_counts[i] = 0.f;
}
__global__ void count_kernel(const int* __restrict__ scope)
{
    int i = blockIdx.x * blockDim.x + threadIdx.x;
    if (i < A_N) atomicAdd(&g_counts[__ldg(&scope[i])], 1.f);
}
__global__ void finalize_kernel(float* __restrict__ out)
{
    int i = blockIdx.x * blockDim.x + threadIdx.x;
    if (i >= NMOLS * HDIM) return;
    out[i] = out[i] / fmaxf(g_counts[i / HDIM], 1.f);
}

// ---------------------------------------------------------------------------
extern "C" void kernel_launch(void* const* d_in, const int* in_sizes, int n_in,
                              void* d_out, int out_size)
{
    const float* fatoms   = (const float*)d_in[0];
    const float* fbonds   = (const float*)d_in[1];
    const int*   agraph   = (const int*)  d_in[2];
    const int*   bgraph   = (const int*)  d_in[3];
    const float* tree_msg = (const float*)d_in[4];
    const int*   scope    = (const int*)  d_in[5];
    const float* W_i      = (const float*)d_in[6];
    const float* W_h      = (const float*)d_in[7];
    const float* W_o_w    = (const float*)d_in[8];
    const float* W_o_b    = (const float*)d_in[9];
    float* out = (float*)d_out;

    float *binput, *msg;
    __nv_bfloat16 *neihi, *neilo, *fbhi, *fblo, *fahi, *falo, *wthi, *wtlo;
    cudaGetSymbolAddress((void**)&binput, g_binput);
    cudaGetSymbolAddress((void**)&msg,    g_msg);
    cudaGetSymbolAddress((void**)&neihi,  g_neihi);
    cudaGetSymbolAddress((void**)&neilo,  g_neilo);
    cudaGetSymbolAddress((void**)&fbhi,   g_fbhi);
    cudaGetSymbolAddress((void**)&fblo,   g_fblo);
    cudaGetSymbolAddress((void**)&fahi,   g_fahi);
    cudaGetSymbolAddress((void**)&falo,   g_falo);
    cudaGetSymbolAddress((void**)&wthi,   g_WThi);
    cudaGetSymbolAddress((void**)&wtlo,   g_WTlo);

    cudaFuncSetAttribute(hgemm_kernel<0, 2>,  cudaFuncAttributeMaxDynamicSharedMemorySize, HG_SMEM);
    cudaFuncSetAttribute(hgemm_kernel<1, 8>,  cudaFuncAttributeMaxDynamicSharedMemorySize, HG_SMEM);
    cudaFuncSetAttribute(hgemm_kernel<2, 10>, cudaFuncAttributeMaxDynamicSharedMemorySize, HG_SMEM);

    const int gridB = (B_N + TILE_M - 1) / TILE_M;   // 3125
    const int gridA = (A_N + TILE_M - 1) / TILE_M;   // 1563
    dim3 gblk(64, 4);

    // 1) prep fbonds split + W_i ; binput = fbonds @ W_i (pre-activation only)
    prep_a_kernel<<<(int)(((size_t)B_N * 64 + 255) / 256), 256>>>(fbonds, B_N, KI, fbhi, fblo);
    prep_w_kernel<0><<<(256 * 64 + 255) / 256, 256>>>(W_i, KI, 64, wthi, wtlo);
    hgemm_kernel<0, 2><<<gridB, 256, HG_SMEM>>>(
        fbhi, fblo, 64, nullptr, nullptr, 0, wthi, wtlo, B_N,
        nullptr, nullptr, nullptr, binput);

    // 2) two message-passing iterations; iter 1 gathers relu(binput) on the fly
    prep_w_kernel<0><<<(256 * 256 + 255) / 256, 256>>>(W_h, HDIM, 256, wthi, wtlo);
    gather_split_kernel<1><<<(B_N + 3) / 4, gblk>>>(bgraph, B_N, tree_msg, binput, neihi, neilo);
    hgemm_kernel<1, 8><<<gridB, 256, HG_SMEM>>>(
        neihi, neilo, HDIM, nullptr, nullptr, 0, wthi, wtlo, B_N,
        binput, nullptr, nullptr, msg);
    gather_split_kernel<0><<<(B_N + 3) / 4, gblk>>>(bgraph, B_N, tree_msg, msg, neihi, neilo);
    hgemm_kernel<1, 8><<<gridB, 256, HG_SMEM>>>(
        neihi, neilo, HDIM, nullptr, nullptr, 0, wthi, wtlo, B_N,
        binput, nullptr, nullptr, msg);

    // 3) atom gather + pooling prep + output GEMM (fused atomic segment-sum)
    gather_split_kernel<0><<<(A_N + 3) / 4, gblk>>>(agraph, A_N, tree_msg, msg, neihi, neilo);
    zero_out_kernel<<<(NMOLS * HDIM + 255) / 256, 256>>>(out);
    count_kernel<<<(A_N + 255) / 256, 256>>>(scope);
    prep_a_kernel<<<(int)(((size_t)A_N * 64 + 255) / 256), 256>>>(fatoms, A_N, AFD, fahi, falo);
    prep_w_kernel<1><<<(256 * 320 + 255) / 256, 256>>>(W_o_w, KO, 320, wthi, wtlo);
    hgemm_kernel<2, 10><<<gridA, 256, HG_SMEM>>>(
        neihi, neilo, HDIM, fahi, falo, 64, wthi, wtlo, A_N,
        nullptr, W_o_b, scope, out);
    finalize_kernel<<<(NMOLS * HDIM + 255) / 256, 256>>>(out);
}

// round 11
// speedup vs baseline: 1.0630x; 1.0335x over previous
#include <cuda_runtime.h>
#include <cuda_bf16.h>
#include <cstdint>

// Problem constants
#define A_N   100000
#define B_N   200000
#define M_N   20000
#define HDIM  256
#define MAXNB 10
#define NMOLS 2000
#define AFD   35
#define KI    40    // fbonds @ W_i
#define KO    291   // [fatoms, nei] @ W_o_w

// Scratch (device globals)
__device__ float g_binput[(size_t)B_N * HDIM];
__device__ float g_msg   [(size_t)B_N * HDIM];
__device__ float g_counts[NMOLS];
// Split bf16 operand buffers
__device__ __nv_bfloat16 g_neihi[(size_t)B_N * HDIM];
__device__ __nv_bfloat16 g_neilo[(size_t)B_N * HDIM];
__device__ __nv_bfloat16 g_fbhi [(size_t)B_N * 64];
__device__ __nv_bfloat16 g_fblo [(size_t)B_N * 64];
__device__ __nv_bfloat16 g_fahi [(size_t)A_N * 64];
__device__ __nv_bfloat16 g_falo [(size_t)A_N * 64];
// Pre-transposed, bf16-split weights: [N=256, KPAD<=320]
__device__ __nv_bfloat16 g_WThi[256 * 320];
__device__ __nv_bfloat16 g_WTlo[256 * 320];

// ---------------------------------------------------------------------------
// Helpers (base-sm_103-legal: ldmatrix / mma.sync / cp.async)
// ---------------------------------------------------------------------------
__device__ __forceinline__ uint32_t smem_u32(const void* p) {
    uint32_t a;
    asm("{ .reg .u64 t; cvta.to.shared.u64 t, %1; cvt.u32.u64 %0, t; }" : "=r"(a) : "l"(p));
    return a;
}
__device__ __forceinline__ void ldsm4(uint32_t* r, uint32_t addr) {
    asm volatile("ldmatrix.sync.aligned.m8n8.x4.shared.b16 {%0,%1,%2,%3}, [%4];"
                 : "=r"(r[0]), "=r"(r[1]), "=r"(r[2]), "=r"(r[3]) : "r"(addr));
}
__device__ __forceinline__ void mma_bf16(float* c, const uint32_t* a, uint32_t b0, uint32_t b1) {
    asm volatile("mma.sync.aligned.m16n8k16.row.col.f32.bf16.bf16.f32 "
                 "{%0,%1,%2,%3},{%4,%5,%6,%7},{%8,%9},{%0,%1,%2,%3};"
                 : "+f"(c[0]), "+f"(c[1]), "+f"(c[2]), "+f"(c[3])
                 : "r"(a[0]), "r"(a[1]), "r"(a[2]), "r"(a[3]), "r"(b0), "r"(b1));
}
__device__ __forceinline__ void cp_async16(uint32_t dst, const void* src) {
    asm volatile("cp.async.cg.shared.global [%0], [%1], 16;" :: "r"(dst), "l"(src));
}
__device__ __forceinline__ void cp_commit() {
    asm volatile("cp.async.commit_group;" ::: "memory");
}
template <int N>
__device__ __forceinline__ void cp_wait_group() {
    asm volatile("cp.async.wait_group %0;" :: "n"(N) : "memory");
}

#define SW128(o) ((o) ^ ((((uint32_t)(o)) >> 3) & 0x70))

__device__ __forceinline__ void split2(float v, unsigned short& h, unsigned short& l) {
    __nv_bfloat16 hb = __float2bfloat16_rn(v);
    float rem = v - __bfloat162float(hb);
    h = __bfloat16_as_ushort(hb);
    l = __bfloat16_as_ushort(__float2bfloat16_rn(rem));
}

// ---------------------------------------------------------------------------
// Gather + sum over MAX_NB neighbor rows of virtual concat [tree ; msg],
// emitting bf16 hi/lo split of the fp32 sum. RELU=1: apply relu to msg-branch
// rows on the fly (msg buffer then holds PRE-activation values, e.g. binput).
// ---------------------------------------------------------------------------
template <int RELU>
__global__ void gather_split_kernel(const int* __restrict__ graph, int rows,
                                    const float* __restrict__ tree,
                                    const float* __restrict__ msg,
                                    __nv_bfloat16* __restrict__ outhi,
                                    __nv_bfloat16* __restrict__ outlo)
{
    int row = blockIdx.x * blockDim.y + threadIdx.y;
    if (row >= rows) return;
    int t = threadIdx.x;  // 0..63
    const int* gr = graph + (size_t)row * MAXNB;
    float4 acc = make_float4(0.f, 0.f, 0.f, 0.f);
#pragma unroll
    for (int j = 0; j < MAXNB; j++) {
        int idx = __ldg(&gr[j]);
        bool isMsg = (idx >= M_N);
        const float* srcp = isMsg ? (msg + (size_t)(idx - M_N) * HDIM)
                                  : (tree + (size_t)idx * HDIM);
        float4 v = __ldg(((const float4*)srcp) + t);
        if (RELU && isMsg) {
            v.x = fmaxf(v.x, 0.f); v.y = fmaxf(v.y, 0.f);
            v.z = fmaxf(v.z, 0.f); v.w = fmaxf(v.w, 0.f);
        }
        acc.x += v.x; acc.y += v.y; acc.z += v.z; acc.w += v.w;
    }
    unsigned short h0,h1,h2,h3,l0,l1,l2,l3;
    split2(acc.x,h0,l0); split2(acc.y,h1,l1); split2(acc.z,h2,l2); split2(acc.w,h3,l3);
    uint2 uh, ul;
    uh.x = (uint32_t)h0 | ((uint32_t)h1 << 16);
    uh.y = (uint32_t)h2 | ((uint32_t)h3 << 16);
    ul.x = (uint32_t)l0 | ((uint32_t)l1 << 16);
    ul.y = (uint32_t)l2 | ((uint32_t)l3 << 16);
    ((uint2*)outhi)[(size_t)row * 64 + t] = uh;
    ((uint2*)outlo)[(size_t)row * 64 + t] = ul;
}

// ---------------------------------------------------------------------------
// Prep: fp32 [rows, inK] -> bf16 hi/lo [rows, 64] zero-padded
// ---------------------------------------------------------------------------
__global__ void prep_a_kernel(const float* __restrict__ in, int rows, int inK,
                              __nv_bfloat16* __restrict__ hi, __nv_bfloat16* __restrict__ lo)
{
    size_t i = (size_t)blockIdx.x * blockDim.x + threadIdx.x;
    if (i >= (size_t)rows * 64) return;
    int r = (int)(i >> 6), k = (int)(i & 63);
    float v = (k < inK) ? __ldg(&in[(size_t)r * inK + k]) : 0.f;
    unsigned short h, l; split2(v, h, l);
    hi[i] = __ushort_as_bfloat16(h);
    lo[i] = __ushort_as_bfloat16(l);
}

// ---------------------------------------------------------------------------
// Weight prep (concat): WT hi/lo [256, Kpad] from two stacked fp32 sources
// W1 [K1, 256] then W2 [K2, 256], zero padded to Kpad.
// ---------------------------------------------------------------------------
__global__ void prep_w_cat_kernel(const float* __restrict__ W1, int K1,
                                  const float* __restrict__ W2, int K2,
                                  int Kpad,
                                  __nv_bfloat16* __restrict__ hi,
                                  __nv_bfloat16* __restrict__ lo)
{
    int i = blockIdx.x * blockDim.x + threadIdx.x;
    if (i >= 256 * Kpad) return;
    int n = i / Kpad, k = i % Kpad;
    float v = 0.f;
    if (k < K1)            v = __ldg(&W1[(size_t)k * 256 + n]);
    else if (k < K1 + K2)  v = __ldg(&W2[(size_t)(k - K1) * 256 + n]);
    unsigned short h, l; split2(v, h, l);
    hi[i] = __ushort_as_bfloat16(h);
    lo[i] = __ushort_as_bfloat16(l);
}

// ---------------------------------------------------------------------------
// Pure bf16 3-split HGEMM (R8 pipeline): 64x256 CTA tile, 256 threads,
// 8 warps (1x8), 64x32 warp tiles. K-stage 64; A double-buffered (2x16KB),
// B single-buffered (64KB, L2-hot) = 96KB -> 2 CTAs/SM.
// For MODE 1/2, the LAST stage sources A from (A2hi,A2lo,strideA2):
//   MODE 1: A = [nei | fbonds]  -> out1 = relu(C) (msg; binput folded into K)
//   MODE 2: A = [nei | fatoms]  -> relu(C + bias) atomicAdd out1[scope[row]]
// MODE 0: A = fbonds only       -> out1 = C (binput, pre-activation)
// ---------------------------------------------------------------------------
#define TILE_M   64
#define ABUF(s)  ((uint32_t)((s) & 1) * 16384)
#define A_LO_OFF 8192
#define B_HI     32768
#define B_LO     65536
#define HG_SMEM  98304

template <int MODE, int NS>
__global__ __launch_bounds__(256, 2)
void hgemm_kernel(const __nv_bfloat16* __restrict__ Ahi,
                  const __nv_bfloat16* __restrict__ Alo,
                  int strideA,
                  const __nv_bfloat16* __restrict__ A2hi,
                  const __nv_bfloat16* __restrict__ A2lo,
                  int strideA2,
                  const __nv_bfloat16* __restrict__ WThi,
                  const __nv_bfloat16* __restrict__ WTlo,
                  int rowsM,
                  const float* __restrict__ bias,
                  const int*   __restrict__ scope,
                  float* __restrict__ out1)
{
    constexpr int KPAD = NS * 64;
    extern __shared__ char smem[];
    const uint32_t sb = smem_u32(smem);
    const int tid  = threadIdx.x;
    const int lane = tid & 31;
    const int wn   = tid >> 5;                 // 1 x 8 warp grid
    const int rowBlock = blockIdx.x * TILE_M;

    // ldmatrix lane-address components
    const int arow  = ((lane >> 3) & 1) * 8 + (lane & 7);
    const int akb   = (lane >> 4) * 16;
    const int bnrow = ((lane >> 4) & 1) * 8 + (lane & 7);
    const int bkb   = ((lane >> 3) & 1) * 16;

    float acc[4][4][4];   // [mi][ni(8cols)][quad]
#pragma unroll
    for (int mi = 0; mi < 4; mi++)
#pragma unroll
        for (int ni = 0; ni < 4; ni++)
#pragma unroll
            for (int e = 0; e < 4; e++) acc[mi][ni][e] = 0.f;

    auto cpA = [&](int s) {   // 64 rows x 64 K bf16 (hi+lo), SW128, 128B rows
        const __nv_bfloat16 *sh, *sl;
        int stride, kk0;
        if (MODE != 0 && s == NS - 1) { sh = A2hi; sl = A2lo; stride = strideA2; kk0 = 0; }
        else                          { sh = Ahi;  sl = Alo;  stride = strideA;  kk0 = s * 64; }
        uint32_t abuf = ABUF(s);
#pragma unroll
        for (int i = 0; i < 2; i++) {
            int idx = i * 256 + tid;          // 512 16B-chunks per half
            int r = idx >> 3, c = idx & 7;
            int grow = rowBlock + r;
            if (grow >= rowsM) grow = rowsM - 1;   // clamp; epilogue guards stores
            uint32_t dsw = SW128(r * 128 + c * 16);
            size_t src = (size_t)grow * stride + kk0 + c * 8;
            cp_async16(sb + abuf + dsw,            sh + src);
            cp_async16(sb + abuf + A_LO_OFF + dsw, sl + src);
        }
    };

    auto cpB = [&](int s) {   // 256 n-rows x 64 K bf16 (hi+lo), SW128
        int k0 = s * 64;
#pragma unroll
        for (int i = 0; i < 8; i++) {
            int idx = i * 256 + tid;          // 2048 16B-chunks per half
            int n = idx >> 3, c = idx & 7;
            uint32_t dsw = SW128(n * 128 + c * 16);
            size_t src = (size_t)n * KPAD + k0 + c * 8;
            cp_async16(sb + B_HI + dsw, WThi + src);
            cp_async16(sb + B_LO + dsw, WTlo + src);
        }
    };

    // Prologue: A(0) in flight as its own group
    cpA(0);
    cp_commit();

    for (int s = 0; s < NS; s++) {
        __syncthreads();            // MMA(s-1) done: B buffer + A[(s+1)&1] free
        cpB(s);
        cp_commit();
        if (s + 1 < NS) {
            cpA(s + 1);
            cp_commit();
            cp_wait_group<1>();     // A(s), B(s) arrived; A(s+1) may be pending
        } else {
            cp_wait_group<0>();
        }
        __syncthreads();

        const uint32_t aBase = sb + ABUF(s);
#pragma unroll
        for (int kk = 0; kk < 4; kk++) {
            uint32_t boff0 = (uint32_t)(wn * 32 + bnrow) * 128 + kk * 32 + bkb;
            uint32_t boff1 = (uint32_t)(wn * 32 + 16 + bnrow) * 128 + kk * 32 + bkb;
            uint32_t bsw0 = SW128(boff0), bsw1 = SW128(boff1);
            // ---- hi-B pass: (ahi + alo) x Bhi ----
            {
                uint32_t b0[4], b1[4];
                ldsm4(b0, sb + B_HI + bsw0);
                ldsm4(b1, sb + B_HI + bsw1);
#pragma unroll
                for (int mi = 0; mi < 4; mi++) {
                    uint32_t aoff = (uint32_t)(mi * 16 + arow) * 128 + kk * 32 + akb;
                    uint32_t asw = SW128(aoff);
                    uint32_t ahi[4], alo[4];
                    ldsm4(ahi, aBase + asw);
                    ldsm4(alo, aBase + A_LO_OFF + asw);
                    mma_bf16(acc[mi][0], ahi, b0[0], b0[1]);
                    mma_bf16(acc[mi][1], ahi, b0[2], b0[3]);
                    mma_bf16(acc[mi][0], alo, b0[0], b0[1]);
                    mma_bf16(acc[mi][1], alo, b0[2], b0[3]);
                    mma_bf16(acc[mi][2], ahi, b1[0], b1[1]);
                    mma_bf16(acc[mi][3], ahi, b1[2], b1[3]);
                    mma_bf16(acc[mi][2], alo, b1[0], b1[1]);
                    mma_bf16(acc[mi][3], alo, b1[2], b1[3]);
                }
            }
            // ---- lo-B pass: ahi x Blo ----
            {
                uint32_t b0[4], b1[4];
                ldsm4(b0, sb + B_LO + bsw0);
                ldsm4(b1, sb + B_LO + bsw1);
#pragma unroll
                for (int mi = 0; mi < 4; mi++) {
                    uint32_t aoff = (uint32_t)(mi * 16 + arow) * 128 + kk * 32 + akb;
                    uint32_t asw = SW128(aoff);
                    uint32_t ahi[4];
                    ldsm4(ahi, aBase + asw);
                    mma_bf16(acc[mi][0], ahi, b0[0], b0[1]);
                    mma_bf16(acc[mi][1], ahi, b0[2], b0[3]);
                    mma_bf16(acc[mi][2], ahi, b1[0], b1[1]);
                    mma_bf16(acc[mi][3], ahi, b1[2], b1[3]);
                }
            }
        }
    }

    // ---- Epilogue ----
#pragma unroll
    for (int mi = 0; mi < 4; mi++) {
        int r0 = rowBlock + mi * 16 + (lane >> 2);
        int r1 = r0 + 8;
        int seg0 = 0, seg1 = 0;
        if (MODE == 2) {
            seg0 = (r0 < rowsM) ? __ldg(&scope[r0]) : 0;
            seg1 = (r1 < rowsM) ? __ldg(&scope[r1]) : 0;
        }
#pragma unroll
        for (int ni = 0; ni < 4; ni++) {
            int col = wn * 32 + ni * 8 + (lane & 3) * 2;
            float* c = acc[mi][ni];
            if (MODE == 0) {
                if (r0 < rowsM)
                    *(float2*)(out1 + (size_t)r0 * HDIM + col) = make_float2(c[0], c[1]);
                if (r1 < rowsM)
                    *(float2*)(out1 + (size_t)r1 * HDIM + col) = make_float2(c[2], c[3]);
            } else if (MODE == 1) {
                if (r0 < rowsM)
                    *(float2*)(out1 + (size_t)r0 * HDIM + col) =
                        make_float2(fmaxf(c[0], 0.f), fmaxf(c[1], 0.f));
                if (r1 < rowsM)
                    *(float2*)(out1 + (size_t)r1 * HDIM + col) =
                        make_float2(fmaxf(c[2], 0.f), fmaxf(c[3], 0.f));
            } else {
                float b0 = __ldg(&bias[col]), b1 = __ldg(&bias[col + 1]);
                if (r0 < rowsM) {
                    atomicAdd(&out1[(size_t)seg0 * HDIM + col],     fmaxf(c[0] + b0, 0.f));
                    atomicAdd(&out1[(size_t)seg0 * HDIM + col + 1], fmaxf(c[1] + b1, 0.f));
                }
                if (r1 < rowsM) {
                    atomicAdd(&out1[(size_t)seg1 * HDIM + col],     fmaxf(c[2] + b0, 0.f));
                    atomicAdd(&out1[(size_t)seg1 * HDIM + col + 1], fmaxf(c[3] + b1, 0.f));
                }
            }
        }
    }
}

// ---------------------------------------------------------------------------
// Pooling helpers
// ---------------------------------------------------------------------------
__global__ void zero_out_kernel(float* __restrict__ out)
{
    int i = blockIdx.x * blockDim.x + threadIdx.x;
    if (i < NMOLS * HDIM) out[i] = 0.f;
    if (i < NMOLS) g_counts[i] = 0.f;
}
__global__ void count_kernel(const int* __restrict__ scope)
{
    int i = blockIdx.x * blockDim.x + threadIdx.x;
    if (i < A_N) atomicAdd(&g_counts[__ldg(&scope[i])], 1.f);
}
__global__ void finalize_kernel(float* __restrict__ out)
{
    int i = blockIdx.x * blockDim.x + threadIdx.x;
    if (i >= NMOLS * HDIM) return;
    out[i] = out[i] / fmaxf(g_counts[i / HDIM], 1.f);
}

// ---------------------------------------------------------------------------
extern "C" void kernel_launch(void* const* d_in, const int* in_sizes, int n_in,
                              void* d_out, int out_size)
{
    const float* fatoms   = (const float*)d_in[0];
    const float* fbonds   = (const float*)d_in[1];
    const int*   agraph   = (const int*)  d_in[2];
    const int*   bgraph   = (const int*)  d_in[3];
    const float* tree_msg = (const float*)d_in[4];
    const int*   scope    = (const int*)  d_in[5];
    const float* W_i      = (const float*)d_in[6];
    const float* W_h      = (const float*)d_in[7];
    const float* W_o_w    = (const float*)d_in[8];
    const float* W_o_b    = (const float*)d_in[9];
    float* out = (float*)d_out;

    float *binput, *msg;
    __nv_bfloat16 *neihi, *neilo, *fbhi, *fblo, *fahi, *falo, *wthi, *wtlo;
    cudaGetSymbolAddress((void**)&binput, g_binput);
    cudaGetSymbolAddress((void**)&msg,    g_msg);
    cudaGetSymbolAddress((void**)&neihi,  g_neihi);
    cudaGetSymbolAddress((void**)&neilo,  g_neilo);
    cudaGetSymbolAddress((void**)&fbhi,   g_fbhi);
    cudaGetSymbolAddress((void**)&fblo,   g_fblo);
    cudaGetSymbolAddress((void**)&fahi,   g_fahi);
    cudaGetSymbolAddress((void**)&falo,   g_falo);
    cudaGetSymbolAddress((void**)&wthi,   g_WThi);
    cudaGetSymbolAddress((void**)&wtlo,   g_WTlo);

    cudaFuncSetAttribute(hgemm_kernel<0, 1>, cudaFuncAttributeMaxDynamicSharedMemorySize, HG_SMEM);
    cudaFuncSetAttribute(hgemm_kernel<1, 5>, cudaFuncAttributeMaxDynamicSharedMemorySize, HG_SMEM);
    cudaFuncSetAttribute(hgemm_kernel<2, 5>, cudaFuncAttributeMaxDynamicSharedMemorySize, HG_SMEM);

    const int gridB = (B_N + TILE_M - 1) / TILE_M;   // 3125
    const int gridA = (A_N + TILE_M - 1) / TILE_M;   // 1563
    dim3 gblk(64, 4);

    // 1) prep fbonds split + W_i ; binput = fbonds @ W_i (pre-activation only)
    prep_a_kernel<<<(int)(((size_t)B_N * 64 + 255) / 256), 256>>>(fbonds, B_N, KI, fbhi, fblo);
    prep_w_cat_kernel<<<(256 * 64 + 255) / 256, 256>>>(W_i, KI, nullptr, 0, 64, wthi, wtlo);
    hgemm_kernel<0, 1><<<gridB, 256, HG_SMEM>>>(
        fbhi, fblo, 64, nullptr, nullptr, 0, wthi, wtlo, B_N,
        nullptr, nullptr, binput);

    // 2) two message-passing iterations with binput folded into K:
    //    msg = relu([nei | fbonds] @ [W_h ; W_i])
    prep_w_cat_kernel<<<(256 * 320 + 255) / 256, 256>>>(W_h, HDIM, W_i, KI, 320, wthi, wtlo);
    gather_split_kernel<1><<<(B_N + 3) / 4, gblk>>>(bgraph, B_N, tree_msg, binput, neihi, neilo);
    hgemm_kernel<1, 5><<<gridB, 256, HG_SMEM>>>(
        neihi, neilo, HDIM, fbhi, fblo, 64, wthi, wtlo, B_N,
        nullptr, nullptr, msg);
    gather_split_kernel<0><<<(B_N + 3) / 4, gblk>>>(bgraph, B_N, tree_msg, msg, neihi, neilo);
    hgemm_kernel<1, 5><<<gridB, 256, HG_SMEM>>>(
        neihi, neilo, HDIM, fbhi, fblo, 64, wthi, wtlo, B_N,
        nullptr, nullptr, msg);

    // 3) atom gather + pooling prep + output GEMM (fused atomic segment-sum)
    //    [nei | fatoms] @ [W_o_w rows 35..290 ; W_o_w rows 0..34]
    gather_split_kernel<0><<<(A_N + 3) / 4, gblk>>>(agraph, A_N, tree_msg, msg, neihi, neilo);
    zero_out_kernel<<<(NMOLS * HDIM + 255) / 256, 256>>>(out);
    count_kernel<<<(A_N + 255) / 256, 256>>>(scope);
    prep_a_kernel<<<(int)(((size_t)A_N * 64 + 255) / 256), 256>>>(fatoms, A_N, AFD, fahi, falo);
    prep_w_cat_kernel<<<(256 * 320 + 255) / 256, 256>>>(W_o_w + (size_t)AFD * 256, KO - AFD,
                                                        W_o_w, AFD, 320, wthi, wtlo);
    hgemm_kernel<2, 5><<<gridA, 256, HG_SMEM>>>(
        neihi, neilo, HDIM, fahi, falo, 64, wthi, wtlo, A_N,
        W_o_b, scope, out);
    finalize_kernel<<<(NMOLS * HDIM + 255) / 256, 256>>>(out);
}

// round 12
// speedup vs baseline: 1.0676x; 1.0044x over previous
#include <cuda_runtime.h>
#include <cuda_bf16.h>
#include <cstdint>

// Problem constants
#define A_N   100000
#define B_N   200000
#define M_N   20000
#define HDIM  256
#define MAXNB 10
#define NMOLS 2000
#define AFD   35
#define KI    40    // fbonds @ W_i
#define KO    291   // [fatoms, nei] @ W_o_w

// Scratch (device globals)
__device__ float g_binput[(size_t)B_N * HDIM];
__device__ float g_msg   [(size_t)B_N * HDIM];
__device__ float g_counts[NMOLS];
// Split bf16 operand buffers
__device__ __nv_bfloat16 g_neihi[(size_t)B_N * HDIM];
__device__ __nv_bfloat16 g_neilo[(size_t)B_N * HDIM];
__device__ __nv_bfloat16 g_fbhi [(size_t)B_N * 64];
__device__ __nv_bfloat16 g_fblo [(size_t)B_N * 64];
__device__ __nv_bfloat16 g_fahi [(size_t)A_N * 64];
__device__ __nv_bfloat16 g_falo [(size_t)A_N * 64];
// Pre-transposed, bf16-split weights: [N=256, KPAD<=320]
__device__ __nv_bfloat16 g_WThi[256 * 320];
__device__ __nv_bfloat16 g_WTlo[256 * 320];

// ---------------------------------------------------------------------------
// Helpers (base-sm_103-legal: ldmatrix / mma.sync / cp.async)
// ---------------------------------------------------------------------------
__device__ __forceinline__ uint32_t smem_u32(const void* p) {
    uint32_t a;
    asm("{ .reg .u64 t; cvta.to.shared.u64 t, %1; cvt.u32.u64 %0, t; }" : "=r"(a) : "l"(p));
    return a;
}
__device__ __forceinline__ void ldsm4(uint32_t* r, uint32_t addr) {
    asm volatile("ldmatrix.sync.aligned.m8n8.x4.shared.b16 {%0,%1,%2,%3}, [%4];"
                 : "=r"(r[0]), "=r"(r[1]), "=r"(r[2]), "=r"(r[3]) : "r"(addr));
}
__device__ __forceinline__ void mma_bf16(float* c, const uint32_t* a, uint32_t b0, uint32_t b1) {
    asm volatile("mma.sync.aligned.m16n8k16.row.col.f32.bf16.bf16.f32 "
                 "{%0,%1,%2,%3},{%4,%5,%6,%7},{%8,%9},{%0,%1,%2,%3};"
                 : "+f"(c[0]), "+f"(c[1]), "+f"(c[2]), "+f"(c[3])
                 : "r"(a[0]), "r"(a[1]), "r"(a[2]), "r"(a[3]), "r"(b0), "r"(b1));
}
__device__ __forceinline__ void cp_async16(uint32_t dst, const void* src) {
    asm volatile("cp.async.cg.shared.global [%0], [%1], 16;" :: "r"(dst), "l"(src));
}
__device__ __forceinline__ void cp_commit() {
    asm volatile("cp.async.commit_group;" ::: "memory");
}
template <int N>
__device__ __forceinline__ void cp_wait_group() {
    asm volatile("cp.async.wait_group %0;" :: "n"(N) : "memory");
}

#define SW128(o) ((o) ^ ((((uint32_t)(o)) >> 3) & 0x70))

__device__ __forceinline__ void split2(float v, unsigned short& h, unsigned short& l) {
    __nv_bfloat16 hb = __float2bfloat16_rn(v);
    float rem = v - __bfloat162float(hb);
    h = __bfloat16_as_ushort(hb);
    l = __bfloat16_as_ushort(__float2bfloat16_rn(rem));
}

// ---------------------------------------------------------------------------
// Gather + sum over MAX_NB neighbor rows of virtual concat [tree ; msg],
// emitting bf16 hi/lo split of the fp32 sum. RELU=1: apply relu to msg-branch
// rows on the fly. 512-thread blocks, preloaded indices, 2 accumulator trees.
// ---------------------------------------------------------------------------
template <int RELU>
__global__ void gather_split_kernel(const int* __restrict__ graph, int rows,
                                    const float* __restrict__ tree,
                                    const float* __restrict__ msg,
                                    __nv_bfloat16* __restrict__ outhi,
                                    __nv_bfloat16* __restrict__ outlo)
{
    int row = blockIdx.x * blockDim.y + threadIdx.y;
    if (row >= rows) return;
    int t = threadIdx.x;  // 0..63
    const int* gr = graph + (size_t)row * MAXNB;
    int idxs[MAXNB];
#pragma unroll
    for (int j = 0; j < MAXNB; j++) idxs[j] = __ldg(&gr[j]);

    const float4* srcs[MAXNB];
    bool im[MAXNB];
#pragma unroll
    for (int j = 0; j < MAXNB; j++) {
        im[j] = (idxs[j] >= M_N);
        srcs[j] = (const float4*)(im[j] ? (msg + (size_t)(idxs[j] - M_N) * HDIM)
                                        : (tree + (size_t)idxs[j] * HDIM)) + t;
    }
    float4 acc0 = make_float4(0.f, 0.f, 0.f, 0.f);
    float4 acc1 = make_float4(0.f, 0.f, 0.f, 0.f);
#pragma unroll
    for (int j = 0; j < MAXNB; j += 2) {
        float4 v0 = __ldg(srcs[j]);
        float4 v1 = __ldg(srcs[j + 1]);
        if (RELU && im[j]) {
            v0.x = fmaxf(v0.x, 0.f); v0.y = fmaxf(v0.y, 0.f);
            v0.z = fmaxf(v0.z, 0.f); v0.w = fmaxf(v0.w, 0.f);
        }
        if (RELU && im[j + 1]) {
            v1.x = fmaxf(v1.x, 0.f); v1.y = fmaxf(v1.y, 0.f);
            v1.z = fmaxf(v1.z, 0.f); v1.w = fmaxf(v1.w, 0.f);
        }
        acc0.x += v0.x; acc0.y += v0.y; acc0.z += v0.z; acc0.w += v0.w;
        acc1.x += v1.x; acc1.y += v1.y; acc1.z += v1.z; acc1.w += v1.w;
    }
    float4 acc = make_float4(acc0.x + acc1.x, acc0.y + acc1.y,
                             acc0.z + acc1.z, acc0.w + acc1.w);
    unsigned short h0,h1,h2,h3,l0,l1,l2,l3;
    split2(acc.x,h0,l0); split2(acc.y,h1,l1); split2(acc.z,h2,l2); split2(acc.w,h3,l3);
    uint2 uh, ul;
    uh.x = (uint32_t)h0 | ((uint32_t)h1 << 16);
    uh.y = (uint32_t)h2 | ((uint32_t)h3 << 16);
    ul.x = (uint32_t)l0 | ((uint32_t)l1 << 16);
    ul.y = (uint32_t)l2 | ((uint32_t)l3 << 16);
    ((uint2*)outhi)[(size_t)row * 64 + t] = uh;
    ((uint2*)outlo)[(size_t)row * 64 + t] = ul;
}

// ---------------------------------------------------------------------------
// Prep: fp32 [rows, inK] -> bf16 hi/lo [rows, 64] zero-padded
// ---------------------------------------------------------------------------
__global__ void prep_a_kernel(const float* __restrict__ in, int rows, int inK,
                              __nv_bfloat16* __restrict__ hi, __nv_bfloat16* __restrict__ lo)
{
    size_t i = (size_t)blockIdx.x * blockDim.x + threadIdx.x;
    if (i >= (size_t)rows * 64) return;
    int r = (int)(i >> 6), k = (int)(i & 63);
    float v = (k < inK) ? __ldg(&in[(size_t)r * inK + k]) : 0.f;
    unsigned short h, l; split2(v, h, l);
    hi[i] = __ushort_as_bfloat16(h);
    lo[i] = __ushort_as_bfloat16(l);
}

// ---------------------------------------------------------------------------
// Weight prep (concat): WT hi/lo [256, Kpad] from two stacked fp32 sources
// ---------------------------------------------------------------------------
__global__ void prep_w_cat_kernel(const float* __restrict__ W1, int K1,
                                  const float* __restrict__ W2, int K2,
                                  int Kpad,
                                  __nv_bfloat16* __restrict__ hi,
                                  __nv_bfloat16* __restrict__ lo)
{
    int i = blockIdx.x * blockDim.x + threadIdx.x;
    if (i >= 256 * Kpad) return;
    int n = i / Kpad, k = i % Kpad;
    float v = 0.f;
    if (k < K1)            v = __ldg(&W1[(size_t)k * 256 + n]);
    else if (k < K1 + K2)  v = __ldg(&W2[(size_t)(k - K1) * 256 + n]);
    unsigned short h, l; split2(v, h, l);
    hi[i] = __ushort_as_bfloat16(h);
    lo[i] = __ushort_as_bfloat16(l);
}

// ---------------------------------------------------------------------------
// bf16 3-split HGEMM with split-B software pipelining.
// 64x256 CTA tile, 256 threads (8 warps, 1x8), 64x32 warp tiles, K-stage 64.
// smem: A double (2x16KB) + B_hi (32KB) + B_lo (32KB) = 96KB -> 2 CTAs/SM.
// Pipeline: Blo(s) streams under the hi-B MMA pass; Bhi(s+1)+A(s+1) stream
// under the lo-B pass. No exposed load latency, no extra smem.
// MODE 0: A = fbonds           -> out1 = C (binput pre-activation)
// MODE 1: A = [nei | fbonds]   -> out1 = relu(C) (binput folded into K)
// MODE 2: A = [nei | fatoms]   -> relu(C + bias) atomicAdd out1[scope[row]]
// (MODE 1/2: last stage sources A from (A2hi,A2lo,strideA2))
// ---------------------------------------------------------------------------
#define TILE_M   64
#define ABUF(s)  ((uint32_t)((s) & 1) * 16384)
#define A_LO_OFF 8192
#define B_HI     32768
#define B_LO     65536
#define HG_SMEM  98304

template <int MODE, int NS>
__global__ __launch_bounds__(256, 2)
void hgemm_kernel(const __nv_bfloat16* __restrict__ Ahi,
                  const __nv_bfloat16* __restrict__ Alo,
                  int strideA,
                  const __nv_bfloat16* __restrict__ A2hi,
                  const __nv_bfloat16* __restrict__ A2lo,
                  int strideA2,
                  const __nv_bfloat16* __restrict__ WThi,
                  const __nv_bfloat16* __restrict__ WTlo,
                  int rowsM,
                  const float* __restrict__ bias,
                  const int*   __restrict__ scope,
                  float* __restrict__ out1)
{
    constexpr int KPAD = NS * 64;
    extern __shared__ char smem[];
    const uint32_t sb = smem_u32(smem);
    const int tid  = threadIdx.x;
    const int lane = tid & 31;
    const int wn   = tid >> 5;                 // 1 x 8 warp grid
    const int rowBlock = blockIdx.x * TILE_M;

    // ldmatrix lane-address components
    const int arow  = ((lane >> 3) & 1) * 8 + (lane & 7);
    const int akb   = (lane >> 4) * 16;
    const int bnrow = ((lane >> 4) & 1) * 8 + (lane & 7);
    const int bkb   = ((lane >> 3) & 1) * 16;

    float acc[4][4][4];   // [mi][ni(8cols)][quad]
#pragma unroll
    for (int mi = 0; mi < 4; mi++)
#pragma unroll
        for (int ni = 0; ni < 4; ni++)
#pragma unroll
            for (int e = 0; e < 4; e++) acc[mi][ni][e] = 0.f;

    auto cpA = [&](int s) {   // 64 rows x 64 K bf16 (hi+lo), SW128
        const __nv_bfloat16 *sh, *sl;
        int stride, kk0;
        if (MODE != 0 && s == NS - 1) { sh = A2hi; sl = A2lo; stride = strideA2; kk0 = 0; }
        else                          { sh = Ahi;  sl = Alo;  stride = strideA;  kk0 = s * 64; }
        uint32_t abuf = ABUF(s);
#pragma unroll
        for (int i = 0; i < 2; i++) {
            int idx = i * 256 + tid;
            int r = idx >> 3, c = idx & 7;
            int grow = rowBlock + r;
            if (grow >= rowsM) grow = rowsM - 1;   // clamp; epilogue guards stores
            uint32_t dsw = SW128(r * 128 + c * 16);
            size_t src = (size_t)grow * stride + kk0 + c * 8;
            cp_async16(sb + abuf + dsw,            sh + src);
            cp_async16(sb + abuf + A_LO_OFF + dsw, sl + src);
        }
    };

    auto cpBhalf = [&](int s, uint32_t dstOff, const __nv_bfloat16* WT) {
        int k0 = s * 64;
#pragma unroll
        for (int i = 0; i < 8; i++) {
            int idx = i * 256 + tid;          // 2048 16B-chunks
            int n = idx >> 3, c = idx & 7;
            uint32_t dsw = SW128(n * 128 + c * 16);
            cp_async16(sb + dstOff + dsw, WT + (size_t)n * KPAD + k0 + c * 8);
        }
    };

    // Prologue: A(0), Bhi(0), Blo(0) as three groups
    cpA(0);                    cp_commit();
    cpBhalf(0, B_HI, WThi);    cp_commit();
    cpBhalf(0, B_LO, WTlo);    cp_commit();

    for (int s = 0; s < NS; s++) {
        const uint32_t aBase = sb + ABUF(s);
        // entry pending (oldest first): [A(s){,Bhi(s)}], [Blo(s)]
        cp_wait_group<1>();        // A(s) + Bhi(s) resident; Blo(s) may fly
        __syncthreads();

        // ---- hi-B pass: (ahi + alo) x Bhi ----
#pragma unroll
        for (int kk = 0; kk < 4; kk++) {
            uint32_t bsw0 = SW128((uint32_t)(wn * 32 + bnrow) * 128 + kk * 32 + bkb);
            uint32_t bsw1 = SW128((uint32_t)(wn * 32 + 16 + bnrow) * 128 + kk * 32 + bkb);
            uint32_t b0[4], b1[4];
            ldsm4(b0, sb + B_HI + bsw0);
            ldsm4(b1, sb + B_HI + bsw1);
#pragma unroll
            for (int mi = 0; mi < 4; mi++) {
                uint32_t asw = SW128((uint32_t)(mi * 16 + arow) * 128 + kk * 32 + akb);
                uint32_t ahi[4], alo[4];
                ldsm4(ahi, aBase + asw);
                ldsm4(alo, aBase + A_LO_OFF + asw);
                mma_bf16(acc[mi][0], ahi, b0[0], b0[1]);
                mma_bf16(acc[mi][1], ahi, b0[2], b0[3]);
                mma_bf16(acc[mi][0], alo, b0[0], b0[1]);
                mma_bf16(acc[mi][1], alo, b0[2], b0[3]);
                mma_bf16(acc[mi][2], ahi, b1[0], b1[1]);
                mma_bf16(acc[mi][3], ahi, b1[2], b1[3]);
                mma_bf16(acc[mi][2], alo, b1[0], b1[1]);
                mma_bf16(acc[mi][3], alo, b1[2], b1[3]);
            }
        }
        __syncthreads();           // Bhi buffer free (all warps done)

        if (s + 1 < NS) {          // stream A(s+1)+Bhi(s+1) under the lo-pass
            cpA(s + 1);
            cpBhalf(s + 1, B_HI, WThi);
            cp_commit();
            cp_wait_group<1>();    // Blo(s) done; [A+Bhi](s+1) may fly
        } else {
            cp_wait_group<0>();    // Blo(s) done
        }
        __syncthreads();

        // ---- lo-B pass: ahi x Blo ----
#pragma unroll
        for (int kk = 0; kk < 4; kk++) {
            uint32_t bsw0 = SW128((uint32_t)(wn * 32 + bnrow) * 128 + kk * 32 + bkb);
            uint32_t bsw1 = SW128((uint32_t)(wn * 32 + 16 + bnrow) * 128 + kk * 32 + bkb);
            uint32_t b0[4], b1[4];
            ldsm4(b0, sb + B_LO + bsw0);
            ldsm4(b1, sb + B_LO + bsw1);
#pragma unroll
            for (int mi = 0; mi < 4; mi++) {
                uint32_t asw = SW128((uint32_t)(mi * 16 + arow) * 128 + kk * 32 + akb);
                uint32_t ahi[4];
                ldsm4(ahi, aBase + asw);
                mma_bf16(acc[mi][0], ahi, b0[0], b0[1]);
                mma_bf16(acc[mi][1], ahi, b0[2], b0[3]);
                mma_bf16(acc[mi][2], ahi, b1[0], b1[1]);
                mma_bf16(acc[mi][3], ahi, b1[2], b1[3]);
            }
        }
        __syncthreads();           // Blo buffer free

        if (s + 1 < NS) {          // stream Blo(s+1) under next hi-pass
            cpBhalf(s + 1, B_LO, WTlo);
            cp_commit();
        }
    }

    // ---- Epilogue ----
#pragma unroll
    for (int mi = 0; mi < 4; mi++) {
        int r0 = rowBlock + mi * 16 + (lane >> 2);
        int r1 = r0 + 8;
        int seg0 = 0, seg1 = 0;
        if (MODE == 2) {
            seg0 = (r0 < rowsM) ? __ldg(&scope[r0]) : 0;
            seg1 = (r1 < rowsM) ? __ldg(&scope[r1]) : 0;
        }
#pragma unroll
        for (int ni = 0; ni < 4; ni++) {
            int col = wn * 32 + ni * 8 + (lane & 3) * 2;
            float* c = acc[mi][ni];
            if (MODE == 0) {
                if (r0 < rowsM)
                    *(float2*)(out1 + (size_t)r0 * HDIM + col) = make_float2(c[0], c[1]);
                if (r1 < rowsM)
                    *(float2*)(out1 + (size_t)r1 * HDIM + col) = make_float2(c[2], c[3]);
            } else if (MODE == 1) {
                if (r0 < rowsM)
                    *(float2*)(out1 + (size_t)r0 * HDIM + col) =
                        make_float2(fmaxf(c[0], 0.f), fmaxf(c[1], 0.f));
                if (r1 < rowsM)
                    *(float2*)(out1 + (size_t)r1 * HDIM + col) =
                        make_float2(fmaxf(c[2], 0.f), fmaxf(c[3], 0.f));
            } else {
                float b0 = __ldg(&bias[col]), b1 = __ldg(&bias[col + 1]);
                if (r0 < rowsM) {
                    atomicAdd(&out1[(size_t)seg0 * HDIM + col],     fmaxf(c[0] + b0, 0.f));
                    atomicAdd(&out1[(size_t)seg0 * HDIM + col + 1], fmaxf(c[1] + b1, 0.f));
                }
                if (r1 < rowsM) {
                    atomicAdd(&out1[(size_t)seg1 * HDIM + col],     fmaxf(c[2] + b0, 0.f));
                    atomicAdd(&out1[(size_t)seg1 * HDIM + col + 1], fmaxf(c[3] + b1, 0.f));
                }
            }
        }
    }
}

// ---------------------------------------------------------------------------
// Pooling helpers
// ---------------------------------------------------------------------------
__global__ void zero_out_kernel(float* __restrict__ out)
{
    int i = blockIdx.x * blockDim.x + threadIdx.x;
    if (i < NMOLS * HDIM) out[i] = 0.f;
    if (i < NMOLS) g_counts[i] = 0.f;
}
__global__ void count_kernel(const int* __restrict__ scope)
{
    int i = blockIdx.x * blockDim.x + threadIdx.x;
    if (i < A_N) atomicAdd(&g_counts[__ldg(&scope[i])], 1.f);
}
__global__ void finalize_kernel(float* __restrict__ out)
{
    int i = blockIdx.x * blockDim.x + threadIdx.x;
    if (i >= NMOLS * HDIM) return;
    out[i] = out[i] / fmaxf(g_counts[i / HDIM], 1.f);
}

// ---------------------------------------------------------------------------
extern "C" void kernel_launch(void* const* d_in, const int* in_sizes, int n_in,
                              void* d_out, int out_size)
{
    const float* fatoms   = (const float*)d_in[0];
    const float* fbonds   = (const float*)d_in[1];
    const int*   agraph   = (const int*)  d_in[2];
    const int*   bgraph   = (const int*)  d_in[3];
    const float* tree_msg = (const float*)d_in[4];
    const int*   scope    = (const int*)  d_in[5];
    const float* W_i      = (const float*)d_in[6];
    const float* W_h      = (const float*)d_in[7];
    const float* W_o_w    = (const float*)d_in[8];
    const float* W_o_b    = (const float*)d_in[9];
    float* out = (float*)d_out;

    float *binput, *msg;
    __nv_bfloat16 *neihi, *neilo, *fbhi, *fblo, *fahi, *falo, *wthi, *wtlo;
    cudaGetSymbolAddress((void**)&binput, g_binput);
    cudaGetSymbolAddress((void**)&msg,    g_msg);
    cudaGetSymbolAddress((void**)&neihi,  g_neihi);
    cudaGetSymbolAddress((void**)&neilo,  g_neilo);
    cudaGetSymbolAddress((void**)&fbhi,   g_fbhi);
    cudaGetSymbolAddress((void**)&fblo,   g_fblo);
    cudaGetSymbolAddress((void**)&fahi,   g_fahi);
    cudaGetSymbolAddress((void**)&falo,   g_falo);
    cudaGetSymbolAddress((void**)&wthi,   g_WThi);
    cudaGetSymbolAddress((void**)&wtlo,   g_WTlo);

    cudaFuncSetAttribute(hgemm_kernel<0, 1>, cudaFuncAttributeMaxDynamicSharedMemorySize, HG_SMEM);
    cudaFuncSetAttribute(hgemm_kernel<1, 5>, cudaFuncAttributeMaxDynamicSharedMemorySize, HG_SMEM);
    cudaFuncSetAttribute(hgemm_kernel<2, 5>, cudaFuncAttributeMaxDynamicSharedMemorySize, HG_SMEM);

    const int gridB = (B_N + TILE_M - 1) / TILE_M;   // 3125
    const int gridA = (A_N + TILE_M - 1) / TILE_M;   // 1563
    dim3 gblk(64, 8);

    // 1) prep fbonds split + W_i ; binput = fbonds @ W_i (pre-activation only)
    prep_a_kernel<<<(int)(((size_t)B_N * 64 + 255) / 256), 256>>>(fbonds, B_N, KI, fbhi, fblo);
    prep_w_cat_kernel<<<(256 * 64 + 255) / 256, 256>>>(W_i, KI, nullptr, 0, 64, wthi, wtlo);
    hgemm_kernel<0, 1><<<gridB, 256, HG_SMEM>>>(
        fbhi, fblo, 64, nullptr, nullptr, 0, wthi, wtlo, B_N,
        nullptr, nullptr, binput);

    // 2) two message-passing iterations with binput folded into K:
    //    msg = relu([nei | fbonds] @ [W_h ; W_i])
    prep_w_cat_kernel<<<(256 * 320 + 255) / 256, 256>>>(W_h, HDIM, W_i, KI, 320, wthi, wtlo);
    gather_split_kernel<1><<<(B_N + 7) / 8, gblk>>>(bgraph, B_N, tree_msg, binput, neihi, neilo);
    hgemm_kernel<1, 5><<<gridB, 256, HG_SMEM>>>(
        neihi, neilo, HDIM, fbhi, fblo, 64, wthi, wtlo, B_N,
        nullptr, nullptr, msg);
    gather_split_kernel<0><<<(B_N + 7) / 8, gblk>>>(bgraph, B_N, tree_msg, msg, neihi, neilo);
    hgemm_kernel<1, 5><<<gridB, 256, HG_SMEM>>>(
        neihi, neilo, HDIM, fbhi, fblo, 64, wthi, wtlo, B_N,
        nullptr, nullptr, msg);

    // 3) atom gather + pooling prep + output GEMM (fused atomic segment-sum)
    //    [nei | fatoms] @ [W_o_w rows 35..290 ; W_o_w rows 0..34]
    gather_split_kernel<0><<<(A_N + 7) / 8, gblk>>>(agraph, A_N, tree_msg, msg, neihi, neilo);
    zero_out_kernel<<<(NMOLS * HDIM + 255) / 256, 256>>>(out);
    count_kernel<<<(A_N + 255) / 256, 256>>>(scope);
    prep_a_kernel<<<(int)(((size_t)A_N * 64 + 255) / 256), 256>>>(fatoms, A_N, AFD, fahi, falo);
    prep_w_cat_kernel<<<(256 * 320 + 255) / 256, 256>>>(W_o_w + (size_t)AFD * 256, KO - AFD,
                                                        W_o_w, AFD, 320, wthi, wtlo);
    hgemm_kernel<2, 5><<<gridA, 256, HG_SMEM>>>(
        neihi, neilo, HDIM, fahi, falo, 64, wthi, wtlo, A_N,
        W_o_b, scope, out);
    finalize_kernel<<<(NMOLS * HDIM + 255) / 256, 256>>>(out);
}

// round 13
// speedup vs baseline: 1.0793x; 1.0109x over previous
#include <cuda_runtime.h>
#include <cuda_bf16.h>
#include <cstdint>

// Problem constants
#define A_N   100000
#define B_N   200000
#define M_N   20000
#define HDIM  256
#define MAXNB 10
#define NMOLS 2000
#define AFD   35
#define KI    40    // fbonds @ W_i
#define KO    291   // [fatoms, nei] @ W_o_w

// Scratch (device globals)
__device__ float g_binput[(size_t)B_N * HDIM];
__device__ float g_msg   [(size_t)B_N * HDIM];
__device__ float g_counts[NMOLS];
// Split bf16 operand buffers
__device__ __nv_bfloat16 g_neihi[(size_t)B_N * HDIM];
__device__ __nv_bfloat16 g_neilo[(size_t)B_N * HDIM];
__device__ __nv_bfloat16 g_fbhi [(size_t)B_N * 64];
__device__ __nv_bfloat16 g_fblo [(size_t)B_N * 64];
__device__ __nv_bfloat16 g_fahi [(size_t)A_N * 64];
__device__ __nv_bfloat16 g_falo [(size_t)A_N * 64];
// Pre-transposed, bf16-split weights: [N=256, KPAD<=320]
__device__ __nv_bfloat16 g_WThi[256 * 320];
__device__ __nv_bfloat16 g_WTlo[256 * 320];

// ---------------------------------------------------------------------------
// Helpers (base-sm_103-legal: ldmatrix / mma.sync / cp.async)
// ---------------------------------------------------------------------------
__device__ __forceinline__ uint32_t smem_u32(const void* p) {
    uint32_t a;
    asm("{ .reg .u64 t; cvta.to.shared.u64 t, %1; cvt.u32.u64 %0, t; }" : "=r"(a) : "l"(p));
    return a;
}
__device__ __forceinline__ void ldsm4(uint32_t* r, uint32_t addr) {
    asm volatile("ldmatrix.sync.aligned.m8n8.x4.shared.b16 {%0,%1,%2,%3}, [%4];"
                 : "=r"(r[0]), "=r"(r[1]), "=r"(r[2]), "=r"(r[3]) : "r"(addr));
}
__device__ __forceinline__ void mma_bf16(float* c, const uint32_t* a, uint32_t b0, uint32_t b1) {
    asm volatile("mma.sync.aligned.m16n8k16.row.col.f32.bf16.bf16.f32 "
                 "{%0,%1,%2,%3},{%4,%5,%6,%7},{%8,%9},{%0,%1,%2,%3};"
                 : "+f"(c[0]), "+f"(c[1]), "+f"(c[2]), "+f"(c[3])
                 : "r"(a[0]), "r"(a[1]), "r"(a[2]), "r"(a[3]), "r"(b0), "r"(b1));
}
__device__ __forceinline__ void cp_async16(uint32_t dst, const void* src) {
    asm volatile("cp.async.cg.shared.global [%0], [%1], 16;" :: "r"(dst), "l"(src));
}
__device__ __forceinline__ void cp_commit() {
    asm volatile("cp.async.commit_group;" ::: "memory");
}
template <int N>
__device__ __forceinline__ void cp_wait_group() {
    asm volatile("cp.async.wait_group %0;" :: "n"(N) : "memory");
}

#define SW128(o) ((o) ^ ((((uint32_t)(o)) >> 3) & 0x70))

__device__ __forceinline__ void split2(float v, unsigned short& h, unsigned short& l) {
    __nv_bfloat16 hb = __float2bfloat16_rn(v);
    float rem = v - __bfloat162float(hb);
    h = __bfloat16_as_ushort(hb);
    l = __bfloat16_as_ushort(__float2bfloat16_rn(rem));
}

// ---------------------------------------------------------------------------
// Gather + sum over MAX_NB neighbor rows of virtual concat [tree ; msg],
// emitting bf16 hi/lo split of the fp32 sum. RELU=1: apply relu to msg-branch
// rows on the fly.
// ---------------------------------------------------------------------------
template <int RELU>
__global__ void gather_split_kernel(const int* __restrict__ graph, int rows,
                                    const float* __restrict__ tree,
                                    const float* __restrict__ msg,
                                    __nv_bfloat16* __restrict__ outhi,
                                    __nv_bfloat16* __restrict__ outlo)
{
    int row = blockIdx.x * blockDim.y + threadIdx.y;
    if (row >= rows) return;
    int t = threadIdx.x;  // 0..63
    const int* gr = graph + (size_t)row * MAXNB;
    int idxs[MAXNB];
#pragma unroll
    for (int j = 0; j < MAXNB; j++) idxs[j] = __ldg(&gr[j]);

    const float4* srcs[MAXNB];
    bool im[MAXNB];
#pragma unroll
    for (int j = 0; j < MAXNB; j++) {
        im[j] = (idxs[j] >= M_N);
        srcs[j] = (const float4*)(im[j] ? (msg + (size_t)(idxs[j] - M_N) * HDIM)
                                        : (tree + (size_t)idxs[j] * HDIM)) + t;
    }
    float4 acc0 = make_float4(0.f, 0.f, 0.f, 0.f);
    float4 acc1 = make_float4(0.f, 0.f, 0.f, 0.f);
#pragma unroll
    for (int j = 0; j < MAXNB; j += 2) {
        float4 v0 = __ldg(srcs[j]);
        float4 v1 = __ldg(srcs[j + 1]);
        if (RELU && im[j]) {
            v0.x = fmaxf(v0.x, 0.f); v0.y = fmaxf(v0.y, 0.f);
            v0.z = fmaxf(v0.z, 0.f); v0.w = fmaxf(v0.w, 0.f);
        }
        if (RELU && im[j + 1]) {
            v1.x = fmaxf(v1.x, 0.f); v1.y = fmaxf(v1.y, 0.f);
            v1.z = fmaxf(v1.z, 0.f); v1.w = fmaxf(v1.w, 0.f);
        }
        acc0.x += v0.x; acc0.y += v0.y; acc0.z += v0.z; acc0.w += v0.w;
        acc1.x += v1.x; acc1.y += v1.y; acc1.z += v1.z; acc1.w += v1.w;
    }
    float4 acc = make_float4(acc0.x + acc1.x, acc0.y + acc1.y,
                             acc0.z + acc1.z, acc0.w + acc1.w);
    unsigned short h0,h1,h2,h3,l0,l1,l2,l3;
    split2(acc.x,h0,l0); split2(acc.y,h1,l1); split2(acc.z,h2,l2); split2(acc.w,h3,l3);
    uint2 uh, ul;
    uh.x = (uint32_t)h0 | ((uint32_t)h1 << 16);
    uh.y = (uint32_t)h2 | ((uint32_t)h3 << 16);
    ul.x = (uint32_t)l0 | ((uint32_t)l1 << 16);
    ul.y = (uint32_t)l2 | ((uint32_t)l3 << 16);
    ((uint2*)outhi)[(size_t)row * 64 + t] = uh;
    ((uint2*)outlo)[(size_t)row * 64 + t] = ul;
}

// ---------------------------------------------------------------------------
// Prep: fp32 [rows, inK] -> bf16 hi/lo [rows, 64] zero-padded
// ---------------------------------------------------------------------------
__global__ void prep_a_kernel(const float* __restrict__ in, int rows, int inK,
                              __nv_bfloat16* __restrict__ hi, __nv_bfloat16* __restrict__ lo)
{
    size_t i = (size_t)blockIdx.x * blockDim.x + threadIdx.x;
    if (i >= (size_t)rows * 64) return;
    int r = (int)(i >> 6), k = (int)(i & 63);
    float v = (k < inK) ? __ldg(&in[(size_t)r * inK + k]) : 0.f;
    unsigned short h, l; split2(v, h, l);
    hi[i] = __ushort_as_bfloat16(h);
    lo[i] = __ushort_as_bfloat16(l);
}

// ---------------------------------------------------------------------------
// Weight prep (concat): WT hi/lo [256, Kpad] from two stacked fp32 sources
// ---------------------------------------------------------------------------
__global__ void prep_w_cat_kernel(const float* __restrict__ W1, int K1,
                                  const float* __restrict__ W2, int K2,
                                  int Kpad,
                                  __nv_bfloat16* __restrict__ hi,
                                  __nv_bfloat16* __restrict__ lo)
{
    int i = blockIdx.x * blockDim.x + threadIdx.x;
    if (i >= 256 * Kpad) return;
    int n = i / Kpad, k = i % Kpad;
    float v = 0.f;
    if (k < K1)            v = __ldg(&W1[(size_t)k * 256 + n]);
    else if (k < K1 + K2)  v = __ldg(&W2[(size_t)(k - K1) * 256 + n]);
    unsigned short h, l; split2(v, h, l);
    hi[i] = __ushort_as_bfloat16(h);
    lo[i] = __ushort_as_bfloat16(l);
}

// ---------------------------------------------------------------------------
// bf16 3-split HGEMM with split-B software pipelining (R12 schedule).
// 64x256 CTA tile, 256 threads (8 warps, 1x8), 64x32 warp tiles, K-stage 64.
// smem: A double (2x16KB) + B_hi (32KB) + B_lo (32KB) = 96KB -> 2 CTAs/SM.
// MODE 0: A = fbonds           -> out1 = C (binput pre-activation)
// MODE 1: A = [nei | fbonds]   -> out1 = relu(C)
// MODE 2: A = [nei | fatoms]   -> run-length segment reduction over the
//         sorted scope (smem staging in dead B buffers), ~2 atomics/col/CTA.
// ---------------------------------------------------------------------------
#define TILE_M   64
#define ABUF(s)  ((uint32_t)((s) & 1) * 16384)
#define A_LO_OFF 8192
#define B_HI     32768
#define B_LO     65536
#define HG_SMEM  98304

template <int MODE, int NS>
__global__ __launch_bounds__(256, 2)
void hgemm_kernel(const __nv_bfloat16* __restrict__ Ahi,
                  const __nv_bfloat16* __restrict__ Alo,
                  int strideA,
                  const __nv_bfloat16* __restrict__ A2hi,
                  const __nv_bfloat16* __restrict__ A2lo,
                  int strideA2,
                  const __nv_bfloat16* __restrict__ WThi,
                  const __nv_bfloat16* __restrict__ WTlo,
                  int rowsM,
                  const float* __restrict__ bias,
                  const int*   __restrict__ scope,
                  float* __restrict__ out1)
{
    constexpr int KPAD = NS * 64;
    extern __shared__ char smem[];
    const uint32_t sb = smem_u32(smem);
    const int tid  = threadIdx.x;
    const int lane = tid & 31;
    const int wn   = tid >> 5;                 // 1 x 8 warp grid
    const int rowBlock = blockIdx.x * TILE_M;

    // ldmatrix lane-address components
    const int arow  = ((lane >> 3) & 1) * 8 + (lane & 7);
    const int akb   = (lane >> 4) * 16;
    const int bnrow = ((lane >> 4) & 1) * 8 + (lane & 7);
    const int bkb   = ((lane >> 3) & 1) * 16;

    float acc[4][4][4];   // [mi][ni(8cols)][quad]
#pragma unroll
    for (int mi = 0; mi < 4; mi++)
#pragma unroll
        for (int ni = 0; ni < 4; ni++)
#pragma unroll
            for (int e = 0; e < 4; e++) acc[mi][ni][e] = 0.f;

    auto cpA = [&](int s) {   // 64 rows x 64 K bf16 (hi+lo), SW128
        const __nv_bfloat16 *sh, *sl;
        int stride, kk0;
        if (MODE != 0 && s == NS - 1) { sh = A2hi; sl = A2lo; stride = strideA2; kk0 = 0; }
        else                          { sh = Ahi;  sl = Alo;  stride = strideA;  kk0 = s * 64; }
        uint32_t abuf = ABUF(s);
#pragma unroll
        for (int i = 0; i < 2; i++) {
            int idx = i * 256 + tid;
            int r = idx >> 3, c = idx & 7;
            int grow = rowBlock + r;
            if (grow >= rowsM) grow = rowsM - 1;   // clamp; epilogue guards
            uint32_t dsw = SW128(r * 128 + c * 16);
            size_t src = (size_t)grow * stride + kk0 + c * 8;
            cp_async16(sb + abuf + dsw,            sh + src);
            cp_async16(sb + abuf + A_LO_OFF + dsw, sl + src);
        }
    };

    auto cpBhalf = [&](int s, uint32_t dstOff, const __nv_bfloat16* WT) {
        int k0 = s * 64;
#pragma unroll
        for (int i = 0; i < 8; i++) {
            int idx = i * 256 + tid;
            int n = idx >> 3, c = idx & 7;
            uint32_t dsw = SW128(n * 128 + c * 16);
            cp_async16(sb + dstOff + dsw, WT + (size_t)n * KPAD + k0 + c * 8);
        }
    };

    // Prologue: A(0), Bhi(0), Blo(0) as three groups
    cpA(0);                    cp_commit();
    cpBhalf(0, B_HI, WThi);    cp_commit();
    cpBhalf(0, B_LO, WTlo);    cp_commit();

    for (int s = 0; s < NS; s++) {
        const uint32_t aBase = sb + ABUF(s);
        cp_wait_group<1>();        // A(s) + Bhi(s) resident; Blo(s) may fly
        __syncthreads();

        // ---- hi-B pass: (ahi + alo) x Bhi ----
#pragma unroll
        for (int kk = 0; kk < 4; kk++) {
            uint32_t bsw0 = SW128((uint32_t)(wn * 32 + bnrow) * 128 + kk * 32 + bkb);
            uint32_t bsw1 = SW128((uint32_t)(wn * 32 + 16 + bnrow) * 128 + kk * 32 + bkb);
            uint32_t b0[4], b1[4];
            ldsm4(b0, sb + B_HI + bsw0);
            ldsm4(b1, sb + B_HI + bsw1);
#pragma unroll
            for (int mi = 0; mi < 4; mi++) {
                uint32_t asw = SW128((uint32_t)(mi * 16 + arow) * 128 + kk * 32 + akb);
                uint32_t ahi[4], alo[4];
                ldsm4(ahi, aBase + asw);
                ldsm4(alo, aBase + A_LO_OFF + asw);
                mma_bf16(acc[mi][0], ahi, b0[0], b0[1]);
                mma_bf16(acc[mi][1], ahi, b0[2], b0[3]);
                mma_bf16(acc[mi][0], alo, b0[0], b0[1]);
                mma_bf16(acc[mi][1], alo, b0[2], b0[3]);
                mma_bf16(acc[mi][2], ahi, b1[0], b1[1]);
                mma_bf16(acc[mi][3], ahi, b1[2], b1[3]);
                mma_bf16(acc[mi][2], alo, b1[0], b1[1]);
                mma_bf16(acc[mi][3], alo, b1[2], b1[3]);
            }
        }
        __syncthreads();           // Bhi buffer free

        if (s + 1 < NS) {          // stream A(s+1)+Bhi(s+1) under the lo-pass
            cpA(s + 1);
            cpBhalf(s + 1, B_HI, WThi);
            cp_commit();
            cp_wait_group<1>();    // Blo(s) done
        } else {
            cp_wait_group<0>();
        }
        __syncthreads();

        // ---- lo-B pass: ahi x Blo ----
#pragma unroll
        for (int kk = 0; kk < 4; kk++) {
            uint32_t bsw0 = SW128((uint32_t)(wn * 32 + bnrow) * 128 + kk * 32 + bkb);
            uint32_t bsw1 = SW128((uint32_t)(wn * 32 + 16 + bnrow) * 128 + kk * 32 + bkb);
            uint32_t b0[4], b1[4];
            ldsm4(b0, sb + B_LO + bsw0);
            ldsm4(b1, sb + B_LO + bsw1);
#pragma unroll
            for (int mi = 0; mi < 4; mi++) {
                uint32_t asw = SW128((uint32_t)(mi * 16 + arow) * 128 + kk * 32 + akb);
                uint32_t ahi[4];
                ldsm4(ahi, aBase + asw);
                mma_bf16(acc[mi][0], ahi, b0[0], b0[1]);
                mma_bf16(acc[mi][1], ahi, b0[2], b0[3]);
                mma_bf16(acc[mi][2], ahi, b1[0], b1[1]);
                mma_bf16(acc[mi][3], ahi, b1[2], b1[3]);
            }
        }
        __syncthreads();           // Blo buffer free

        if (s + 1 < NS) {
            cpBhalf(s + 1, B_LO, WTlo);
            cp_commit();
        }
    }

    // ---- Epilogue ----
    if (MODE == 2) {
        // Stage relu(C + bias) into dead B smem as T[64][256] (row-major),
        // then run-length reduce along sorted scope -> ~2 atomics/col/CTA.
        float* T    = (float*)(smem + B_HI);   // 64KB: B_HI..end
        int*   segs = (int*)(smem);            // 256B in dead A buffer
        if (tid < TILE_M) {
            int gr = rowBlock + tid;
            if (gr >= rowsM) gr = rowsM - 1;
            segs[tid] = __ldg(&scope[gr]);
        }
#pragma unroll
        for (int mi = 0; mi < 4; mi++) {
            int rl0 = mi * 16 + (lane >> 2);
            int rl1 = rl0 + 8;
            bool v0 = (rowBlock + rl0 < rowsM);
            bool v1 = (rowBlock + rl1 < rowsM);
#pragma unroll
            for (int ni = 0; ni < 4; ni++) {
                int col = wn * 32 + ni * 8 + (lane & 3) * 2;
                float b0 = __ldg(&bias[col]), b1 = __ldg(&bias[col + 1]);
                float* c = acc[mi][ni];
                *(float2*)(T + rl0 * 256 + col) = v0
                    ? make_float2(fmaxf(c[0] + b0, 0.f), fmaxf(c[1] + b1, 0.f))
                    : make_float2(0.f, 0.f);
                *(float2*)(T + rl1 * 256 + col) = v1
                    ? make_float2(fmaxf(c[2] + b0, 0.f), fmaxf(c[3] + b1, 0.f))
                    : make_float2(0.f, 0.f);
            }
        }
        __syncthreads();
        // Column walk: thread tid owns column tid.
        {
            int c = tid;
            int cur = segs[0];
            float sum = 0.f;
            for (int r = 0; r < TILE_M; r++) {
                int sg = segs[r];
                float v = T[r * 256 + c];
                if (sg != cur) {
                    atomicAdd(&out1[(size_t)cur * HDIM + c], sum);
                    sum = 0.f; cur = sg;
                }
                sum += v;
            }
            atomicAdd(&out1[(size_t)cur * HDIM + c], sum);
        }
        return;
    }

#pragma unroll
    for (int mi = 0; mi < 4; mi++) {
        int r0 = rowBlock + mi * 16 + (lane >> 2);
        int r1 = r0 + 8;
#pragma unroll
        for (int ni = 0; ni < 4; ni++) {
            int col = wn * 32 + ni * 8 + (lane & 3) * 2;
            float* c = acc[mi][ni];
            if (MODE == 0) {
                if (r0 < rowsM)
                    *(float2*)(out1 + (size_t)r0 * HDIM + col) = make_float2(c[0], c[1]);
                if (r1 < rowsM)
                    *(float2*)(out1 + (size_t)r1 * HDIM + col) = make_float2(c[2], c[3]);
            } else {
                if (r0 < rowsM)
                    *(float2*)(out1 + (size_t)r0 * HDIM + col) =
                        make_float2(fmaxf(c[0], 0.f), fmaxf(c[1], 0.f));
                if (r1 < rowsM)
                    *(float2*)(out1 + (size_t)r1 * HDIM + col) =
                        make_float2(fmaxf(c[2], 0.f), fmaxf(c[3], 0.f));
            }
        }
    }
}

// ---------------------------------------------------------------------------
// Pooling helpers
// ---------------------------------------------------------------------------
__global__ void zero_out_kernel(float* __restrict__ out)
{
    int i = blockIdx.x * blockDim.x + threadIdx.x;
    if (i < NMOLS * HDIM) out[i] = 0.f;
    if (i < NMOLS) g_counts[i] = 0.f;
}
__global__ void count_kernel(const int* __restrict__ scope)
{
    int i = blockIdx.x * blockDim.x + threadIdx.x;
    if (i < A_N) atomicAdd(&g_counts[__ldg(&scope[i])], 1.f);
}
__global__ void finalize_kernel(float* __restrict__ out)
{
    int i = blockIdx.x * blockDim.x + threadIdx.x;
    if (i >= NMOLS * HDIM) return;
    out[i] = out[i] / fmaxf(g_counts[i / HDIM], 1.f);
}

// ---------------------------------------------------------------------------
extern "C" void kernel_launch(void* const* d_in, const int* in_sizes, int n_in,
                              void* d_out, int out_size)
{
    const float* fatoms   = (const float*)d_in[0];
    const float* fbonds   = (const float*)d_in[1];
    const int*   agraph   = (const int*)  d_in[2];
    const int*   bgraph   = (const int*)  d_in[3];
    const float* tree_msg = (const float*)d_in[4];
    const int*   scope    = (const int*)  d_in[5];
    const float* W_i      = (const float*)d_in[6];
    const float* W_h      = (const float*)d_in[7];
    const float* W_o_w    = (const float*)d_in[8];
    const float* W_o_b    = (const float*)d_in[9];
    float* out = (float*)d_out;

    float *binput, *msg;
    __nv_bfloat16 *neihi, *neilo, *fbhi, *fblo, *fahi, *falo, *wthi, *wtlo;
    cudaGetSymbolAddress((void**)&binput, g_binput);
    cudaGetSymbolAddress((void**)&msg,    g_msg);
    cudaGetSymbolAddress((void**)&neihi,  g_neihi);
    cudaGetSymbolAddress((void**)&neilo,  g_neilo);
    cudaGetSymbolAddress((void**)&fbhi,   g_fbhi);
    cudaGetSymbolAddress((void**)&fblo,   g_fblo);
    cudaGetSymbolAddress((void**)&fahi,   g_fahi);
    cudaGetSymbolAddress((void**)&falo,   g_falo);
    cudaGetSymbolAddress((void**)&wthi,   g_WThi);
    cudaGetSymbolAddress((void**)&wtlo,   g_WTlo);

    cudaFuncSetAttribute(hgemm_kernel<0, 1>, cudaFuncAttributeMaxDynamicSharedMemorySize, HG_SMEM);
    cudaFuncSetAttribute(hgemm_kernel<1, 5>, cudaFuncAttributeMaxDynamicSharedMemorySize, HG_SMEM);
    cudaFuncSetAttribute(hgemm_kernel<2, 5>, cudaFuncAttributeMaxDynamicSharedMemorySize, HG_SMEM);

    const int gridB = (B_N + TILE_M - 1) / TILE_M;   // 3125
    const int gridA = (A_N + TILE_M - 1) / TILE_M;   // 1563
    dim3 gblk(64, 8);

    // 0) independent prep / pooling init up front
    zero_out_kernel<<<(NMOLS * HDIM + 255) / 256, 256>>>(out);
    count_kernel<<<(A_N + 255) / 256, 256>>>(scope);
    prep_a_kernel<<<(int)(((size_t)A_N * 64 + 255) / 256), 256>>>(fatoms, A_N, AFD, fahi, falo);

    // 1) prep fbonds split + W_i ; binput = fbonds @ W_i (pre-activation only)
    prep_a_kernel<<<(int)(((size_t)B_N * 64 + 255) / 256), 256>>>(fbonds, B_N, KI, fbhi, fblo);
    prep_w_cat_kernel<<<(256 * 64 + 255) / 256, 256>>>(W_i, KI, nullptr, 0, 64, wthi, wtlo);
    hgemm_kernel<0, 1><<<gridB, 256, HG_SMEM>>>(
        fbhi, fblo, 64, nullptr, nullptr, 0, wthi, wtlo, B_N,
        nullptr, nullptr, binput);

    // 2) two message-passing iterations with binput folded into K:
    //    msg = relu([nei | fbonds] @ [W_h ; W_i])
    prep_w_cat_kernel<<<(256 * 320 + 255) / 256, 256>>>(W_h, HDIM, W_i, KI, 320, wthi, wtlo);
    gather_split_kernel<1><<<(B_N + 7) / 8, gblk>>>(bgraph, B_N, tree_msg, binput, neihi, neilo);
    hgemm_kernel<1, 5><<<gridB, 256, HG_SMEM>>>(
        neihi, neilo, HDIM, fbhi, fblo, 64, wthi, wtlo, B_N,
        nullptr, nullptr, msg);
    gather_split_kernel<0><<<(B_N + 7) / 8, gblk>>>(bgraph, B_N, tree_msg, msg, neihi, neilo);
    hgemm_kernel<1, 5><<<gridB, 256, HG_SMEM>>>(
        neihi, neilo, HDIM, fbhi, fblo, 64, wthi, wtlo, B_N,
        nullptr, nullptr, msg);

    // 3) atom gather + output GEMM (run-length fused segment-sum)
    gather_split_kernel<0><<<(A_N + 7) / 8, gblk>>>(agraph, A_N, tree_msg, msg, neihi, neilo);
    prep_w_cat_kernel<<<(256 * 320 + 255) / 256, 256>>>(W_o_w + (size_t)AFD * 256, KO - AFD,
                                                        W_o_w, AFD, 320, wthi, wtlo);
    hgemm_kernel<2, 5><<<gridA, 256, HG_SMEM>>>(
        neihi, neilo, HDIM, fahi, falo, 64, wthi, wtlo, A_N,
        W_o_b, scope, out);
    finalize_kernel<<<(NMOLS * HDIM + 255) / 256, 256>>>(out);
}

// round 15
// speedup vs baseline: 1.1043x; 1.0232x over previous
#include <cuda_runtime.h>
#include <cuda_bf16.h>
#include <cstdint>

// Problem constants
#define A_N   100000
#define B_N   200000
#define M_N   20000
#define HDIM  256
#define MAXNB 10
#define NMOLS 2000
#define AFD   35
#define KI    40    // fbonds @ W_i
#define KO    291   // [fatoms, nei] @ W_o_w

// Scratch (device globals)
__device__ float g_binput[(size_t)B_N * HDIM];
__device__ float g_msg   [(size_t)B_N * HDIM];
__device__ float g_counts[NMOLS];
// Split bf16 operand buffers
__device__ __nv_bfloat16 g_neihi[(size_t)B_N * HDIM];
__device__ __nv_bfloat16 g_neilo[(size_t)B_N * HDIM];
__device__ __nv_bfloat16 g_fbhi [(size_t)B_N * 64];
__device__ __nv_bfloat16 g_fblo [(size_t)B_N * 64];
__device__ __nv_bfloat16 g_fahi [(size_t)A_N * 64];
__device__ __nv_bfloat16 g_falo [(size_t)A_N * 64];
// Pre-transposed, bf16-split weights: [N=256, KPAD<=320]
__device__ __nv_bfloat16 g_WThi[256 * 320];
__device__ __nv_bfloat16 g_WTlo[256 * 320];

// ---------------------------------------------------------------------------
// Helpers (base-sm_103-legal: ldmatrix / mma.sync / cp.async)
// ---------------------------------------------------------------------------
__device__ __forceinline__ uint32_t smem_u32(const void* p) {
    uint32_t a;
    asm("{ .reg .u64 t; cvta.to.shared.u64 t, %1; cvt.u32.u64 %0, t; }" : "=r"(a) : "l"(p));
    return a;
}
__device__ __forceinline__ void ldsm4(uint32_t* r, uint32_t addr) {
    asm volatile("ldmatrix.sync.aligned.m8n8.x4.shared.b16 {%0,%1,%2,%3}, [%4];"
                 : "=r"(r[0]), "=r"(r[1]), "=r"(r[2]), "=r"(r[3]) : "r"(addr));
}
__device__ __forceinline__ void mma_bf16(float* c, const uint32_t* a, uint32_t b0, uint32_t b1) {
    asm volatile("mma.sync.aligned.m16n8k16.row.col.f32.bf16.bf16.f32 "
                 "{%0,%1,%2,%3},{%4,%5,%6,%7},{%8,%9},{%0,%1,%2,%3};"
                 : "+f"(c[0]), "+f"(c[1]), "+f"(c[2]), "+f"(c[3])
                 : "r"(a[0]), "r"(a[1]), "r"(a[2]), "r"(a[3]), "r"(b0), "r"(b1));
}
__device__ __forceinline__ void cp_async16(uint32_t dst, const void* src) {
    asm volatile("cp.async.cg.shared.global [%0], [%1], 16;" :: "r"(dst), "l"(src));
}
__device__ __forceinline__ void cp_commit() {
    asm volatile("cp.async.commit_group;" ::: "memory");
}
template <int N>
__device__ __forceinline__ void cp_wait_group() {
    asm volatile("cp.async.wait_group %0;" :: "n"(N) : "memory");
}

#define SW128(o) ((o) ^ ((((uint32_t)(o)) >> 3) & 0x70))

__device__ __forceinline__ void split2(float v, unsigned short& h, unsigned short& l) {
    __nv_bfloat16 hb = __float2bfloat16_rn(v);
    float rem = v - __bfloat162float(hb);
    h = __bfloat16_as_ushort(hb);
    l = __bfloat16_as_ushort(__float2bfloat16_rn(rem));
}

// ---------------------------------------------------------------------------
// Gather + sum over MAX_NB neighbor rows of virtual concat [tree ; msg],
// emitting bf16 hi/lo split of the fp32 sum. RELU=1: apply relu to msg-branch
// rows on the fly.
// ---------------------------------------------------------------------------
template <int RELU>
__global__ void gather_split_kernel(const int* __restrict__ graph, int rows,
                                    const float* __restrict__ tree,
                                    const float* __restrict__ msg,
                                    __nv_bfloat16* __restrict__ outhi,
                                    __nv_bfloat16* __restrict__ outlo)
{
    int row = blockIdx.x * blockDim.y + threadIdx.y;
    if (row >= rows) return;
    int t = threadIdx.x;  // 0..63
    const int* gr = graph + (size_t)row * MAXNB;
    int idxs[MAXNB];
#pragma unroll
    for (int j = 0; j < MAXNB; j++) idxs[j] = __ldg(&gr[j]);

    const float4* srcs[MAXNB];
    bool im[MAXNB];
#pragma unroll
    for (int j = 0; j < MAXNB; j++) {
        im[j] = (idxs[j] >= M_N);
        srcs[j] = (const float4*)(im[j] ? (msg + (size_t)(idxs[j] - M_N) * HDIM)
                                        : (tree + (size_t)idxs[j] * HDIM)) + t;
    }
    float4 acc0 = make_float4(0.f, 0.f, 0.f, 0.f);
    float4 acc1 = make_float4(0.f, 0.f, 0.f, 0.f);
#pragma unroll
    for (int j = 0; j < MAXNB; j += 2) {
        float4 v0 = __ldg(srcs[j]);
        float4 v1 = __ldg(srcs[j + 1]);
        if (RELU && im[j]) {
            v0.x = fmaxf(v0.x, 0.f); v0.y = fmaxf(v0.y, 0.f);
            v0.z = fmaxf(v0.z, 0.f); v0.w = fmaxf(v0.w, 0.f);
        }
        if (RELU && im[j + 1]) {
            v1.x = fmaxf(v1.x, 0.f); v1.y = fmaxf(v1.y, 0.f);
            v1.z = fmaxf(v1.z, 0.f); v1.w = fmaxf(v1.w, 0.f);
        }
        acc0.x += v0.x; acc0.y += v0.y; acc0.z += v0.z; acc0.w += v0.w;
        acc1.x += v1.x; acc1.y += v1.y; acc1.z += v1.z; acc1.w += v1.w;
    }
    float4 acc = make_float4(acc0.x + acc1.x, acc0.y + acc1.y,
                             acc0.z + acc1.z, acc0.w + acc1.w);
    unsigned short h0,h1,h2,h3,l0,l1,l2,l3;
    split2(acc.x,h0,l0); split2(acc.y,h1,l1); split2(acc.z,h2,l2); split2(acc.w,h3,l3);
    uint2 uh, ul;
    uh.x = (uint32_t)h0 | ((uint32_t)h1 << 16);
    uh.y = (uint32_t)h2 | ((uint32_t)h3 << 16);
    ul.x = (uint32_t)l0 | ((uint32_t)l1 << 16);
    ul.y = (uint32_t)l2 | ((uint32_t)l3 << 16);
    ((uint2*)outhi)[(size_t)row * 64 + t] = uh;
    ((uint2*)outlo)[(size_t)row * 64 + t] = ul;
}

// ---------------------------------------------------------------------------
// Vectorized prep: fp32 [rows, inK] -> bf16 hi/lo [rows, 64] zero-padded.
// One thread = 4 consecutive k of one row. float4 fast path ONLY when the
// address is provably 16B-aligned (inK % 4 == 0 and fully in-bounds);
// otherwise scalar loads (e.g. fatoms inK=35, row base not 16B-aligned).
// ---------------------------------------------------------------------------
__global__ void prep_a_kernel(const float* __restrict__ in, int rows, int inK,
                              __nv_bfloat16* __restrict__ hi, __nv_bfloat16* __restrict__ lo)
{
    size_t idx = (size_t)blockIdx.x * blockDim.x + threadIdx.x;   // r*16 + kq
    if (idx >= (size_t)rows * 16) return;
    int r  = (int)(idx >> 4);
    int gc = (int)(idx & 15) * 4;
    float4 v;
    if ((inK & 3) == 0 && gc + 3 < inK) {
        v = __ldg((const float4*)(in + (size_t)r * inK + gc));
    } else {
        const float* rp = in + (size_t)r * inK;
        v.x = (gc + 0 < inK) ? __ldg(rp + gc + 0) : 0.f;
        v.y = (gc + 1 < inK) ? __ldg(rp + gc + 1) : 0.f;
        v.z = (gc + 2 < inK) ? __ldg(rp + gc + 2) : 0.f;
        v.w = (gc + 3 < inK) ? __ldg(rp + gc + 3) : 0.f;
    }
    unsigned short h0,h1,h2,h3,l0,l1,l2,l3;
    split2(v.x,h0,l0); split2(v.y,h1,l1); split2(v.z,h2,l2); split2(v.w,h3,l3);
    uint2 uh, ul;
    uh.x = (uint32_t)h0 | ((uint32_t)h1 << 16);
    uh.y = (uint32_t)h2 | ((uint32_t)h3 << 16);
    ul.x = (uint32_t)l0 | ((uint32_t)l1 << 16);
    ul.y = (uint32_t)l2 | ((uint32_t)l3 << 16);
    ((uint2*)hi)[idx] = uh;
    ((uint2*)lo)[idx] = ul;
}

// ---------------------------------------------------------------------------
// Weight prep (concat): WT hi/lo [256, Kpad] from two stacked fp32 sources
// ---------------------------------------------------------------------------
__global__ void prep_w_cat_kernel(const float* __restrict__ W1, int K1,
                                  const float* __restrict__ W2, int K2,
                                  int Kpad,
                                  __nv_bfloat16* __restrict__ hi,
                                  __nv_bfloat16* __restrict__ lo)
{
    int i = blockIdx.x * blockDim.x + threadIdx.x;
    if (i >= 256 * Kpad) return;
    int n = i / Kpad, k = i % Kpad;
    float v = 0.f;
    if (k < K1)            v = __ldg(&W1[(size_t)k * 256 + n]);
    else if (k < K1 + K2)  v = __ldg(&W2[(size_t)(k - K1) * 256 + n]);
    unsigned short h, l; split2(v, h, l);
    hi[i] = __ushort_as_bfloat16(h);
    lo[i] = __ushort_as_bfloat16(l);
}

// ---------------------------------------------------------------------------
// bf16 3-split HGEMM with split-B software pipelining (R12 schedule).
// 64x256 CTA tile, 256 threads (8 warps, 1x8), 64x32 warp tiles, K-stage 64.
// smem: A double (2x16KB) + B_hi (32KB) + B_lo (32KB) = 96KB -> 2 CTAs/SM.
// MODE 0: A = fbonds           -> out1 = C (binput pre-activation)
// MODE 1: A = [nei | fbonds]   -> out1 = relu(C)
// MODE 2: A = [nei | fatoms]   -> run-length segment reduction over the
//         sorted scope (smem staging in dead B buffers), ~2 atomics/col/CTA.
// ---------------------------------------------------------------------------
#define TILE_M   64
#define ABUF(s)  ((uint32_t)((s) & 1) * 16384)
#define A_LO_OFF 8192
#define B_HI     32768
#define B_LO     65536
#define HG_SMEM  98304

template <int MODE, int NS>
__global__ __launch_bounds__(256, 2)
void hgemm_kernel(const __nv_bfloat16* __restrict__ Ahi,
                  const __nv_bfloat16* __restrict__ Alo,
                  int strideA,
                  const __nv_bfloat16* __restrict__ A2hi,
                  const __nv_bfloat16* __restrict__ A2lo,
                  int strideA2,
                  const __nv_bfloat16* __restrict__ WThi,
                  const __nv_bfloat16* __restrict__ WTlo,
                  int rowsM,
                  const float* __restrict__ bias,
                  const int*   __restrict__ scope,
                  float* __restrict__ out1)
{
    constexpr int KPAD = NS * 64;
    extern __shared__ char smem[];
    const uint32_t sb = smem_u32(smem);
    const int tid  = threadIdx.x;
    const int lane = tid & 31;
    const int wn   = tid >> 5;                 // 1 x 8 warp grid
    const int rowBlock = blockIdx.x * TILE_M;

    // ldmatrix lane-address components
    const int arow  = ((lane >> 3) & 1) * 8 + (lane & 7);
    const int akb   = (lane >> 4) * 16;
    const int bnrow = ((lane >> 4) & 1) * 8 + (lane & 7);
    const int bkb   = ((lane >> 3) & 1) * 16;

    float acc[4][4][4];   // [mi][ni(8cols)][quad]
#pragma unroll
    for (int mi = 0; mi < 4; mi++)
#pragma unroll
        for (int ni = 0; ni < 4; ni++)
#pragma unroll
            for (int e = 0; e < 4; e++) acc[mi][ni][e] = 0.f;

    auto cpA = [&](int s) {   // 64 rows x 64 K bf16 (hi+lo), SW128
        const __nv_bfloat16 *sh, *sl;
        int stride, kk0;
        if (MODE != 0 && s == NS - 1) { sh = A2hi; sl = A2lo; stride = strideA2; kk0 = 0; }
        else                          { sh = Ahi;  sl = Alo;  stride = strideA;  kk0 = s * 64; }
        uint32_t abuf = ABUF(s);
#pragma unroll
        for (int i = 0; i < 2; i++) {
            int idx = i * 256 + tid;
            int r = idx >> 3, c = idx & 7;
            int grow = rowBlock + r;
            if (grow >= rowsM) grow = rowsM - 1;   // clamp; epilogue guards
            uint32_t dsw = SW128(r * 128 + c * 16);
            size_t src = (size_t)grow * stride + kk0 + c * 8;
            cp_async16(sb + abuf + dsw,            sh + src);
            cp_async16(sb + abuf + A_LO_OFF + dsw, sl + src);
        }
    };

    auto cpBhalf = [&](int s, uint32_t dstOff, const __nv_bfloat16* WT) {
        int k0 = s * 64;
#pragma unroll
        for (int i = 0; i < 8; i++) {
            int idx = i * 256 + tid;
            int n = idx >> 3, c = idx & 7;
            uint32_t dsw = SW128(n * 128 + c * 16);
            cp_async16(sb + dstOff + dsw, WT + (size_t)n * KPAD + k0 + c * 8);
        }
    };

    // Prologue: A(0), Bhi(0), Blo(0) as three groups
    cpA(0);                    cp_commit();
    cpBhalf(0, B_HI, WThi);    cp_commit();
    cpBhalf(0, B_LO, WTlo);    cp_commit();

    for (int s = 0; s < NS; s++) {
        const uint32_t aBase = sb + ABUF(s);
        cp_wait_group<1>();        // A(s) + Bhi(s) resident; Blo(s) may fly
        __syncthreads();

        // ---- hi-B pass: (ahi + alo) x Bhi ----
#pragma unroll
        for (int kk = 0; kk < 4; kk++) {
            uint32_t bsw0 = SW128((uint32_t)(wn * 32 + bnrow) * 128 + kk * 32 + bkb);
            uint32_t bsw1 = SW128((uint32_t)(wn * 32 + 16 + bnrow) * 128 + kk * 32 + bkb);
            uint32_t b0[4], b1[4];
            ldsm4(b0, sb + B_HI + bsw0);
            ldsm4(b1, sb + B_HI + bsw1);
#pragma unroll
            for (int mi = 0; mi < 4; mi++) {
                uint32_t asw = SW128((uint32_t)(mi * 16 + arow) * 128 + kk * 32 + akb);
                uint32_t ahi[4], alo[4];
                ldsm4(ahi, aBase + asw);
                ldsm4(alo, aBase + A_LO_OFF + asw);
                mma_bf16(acc[mi][0], ahi, b0[0], b0[1]);
                mma_bf16(acc[mi][1], ahi, b0[2], b0[3]);
                mma_bf16(acc[mi][0], alo, b0[0], b0[1]);
                mma_bf16(acc[mi][1], alo, b0[2], b0[3]);
                mma_bf16(acc[mi][2], ahi, b1[0], b1[1]);
                mma_bf16(acc[mi][3], ahi, b1[2], b1[3]);
                mma_bf16(acc[mi][2], alo, b1[0], b1[1]);
                mma_bf16(acc[mi][3], alo, b1[2], b1[3]);
            }
        }
        __syncthreads();           // Bhi buffer free

        if (s + 1 < NS) {          // stream A(s+1)+Bhi(s+1) under the lo-pass
            cpA(s + 1);
            cpBhalf(s + 1, B_HI, WThi);
            cp_commit();
            cp_wait_group<1>();    // Blo(s) done
        } else {
            cp_wait_group<0>();
        }
        __syncthreads();

        // ---- lo-B pass: ahi x Blo ----
#pragma unroll
        for (int kk = 0; kk < 4; kk++) {
            uint32_t bsw0 = SW128((uint32_t)(wn * 32 + bnrow) * 128 + kk * 32 + bkb);
            uint32_t bsw1 = SW128((uint32_t)(wn * 32 + 16 + bnrow) * 128 + kk * 32 + bkb);
            uint32_t b0[4], b1[4];
            ldsm4(b0, sb + B_LO + bsw0);
            ldsm4(b1, sb + B_LO + bsw1);
#pragma unroll
            for (int mi = 0; mi < 4; mi++) {
                uint32_t asw = SW128((uint32_t)(mi * 16 + arow) * 128 + kk * 32 + akb);
                uint32_t ahi[4];
                ldsm4(ahi, aBase + asw);
                mma_bf16(acc[mi][0], ahi, b0[0], b0[1]);
                mma_bf16(acc[mi][1], ahi, b0[2], b0[3]);
                mma_bf16(acc[mi][2], ahi, b1[0], b1[1]);
                mma_bf16(acc[mi][3], ahi, b1[2], b1[3]);
            }
        }
        __syncthreads();           // Blo buffer free

        if (s + 1 < NS) {
            cpBhalf(s + 1, B_LO, WTlo);
            cp_commit();
        }
    }

    // ---- Epilogue ----
    if (MODE == 2) {
        // Stage relu(C + bias) into dead B smem as T[64][256], then run-length
        // reduce along sorted scope -> ~2 atomics/col/CTA.
        float* T    = (float*)(smem + B_HI);   // 64KB: B_HI..end
        int*   segs = (int*)(smem);            // 256B in dead A buffer
        if (tid < TILE_M) {
            int gr = rowBlock + tid;
            if (gr >= rowsM) gr = rowsM - 1;
            segs[tid] = __ldg(&scope[gr]);
        }
#pragma unroll
        for (int mi = 0; mi < 4; mi++) {
            int rl0 = mi * 16 + (lane >> 2);
            int rl1 = rl0 + 8;
            bool v0 = (rowBlock + rl0 < rowsM);
            bool v1 = (rowBlock + rl1 < rowsM);
#pragma unroll
            for (int ni = 0; ni < 4; ni++) {
                int col = wn * 32 + ni * 8 + (lane & 3) * 2;
                float b0 = __ldg(&bias[col]), b1 = __ldg(&bias[col + 1]);
                float* c = acc[mi][ni];
                *(float2*)(T + rl0 * 256 + col) = v0
                    ? make_float2(fmaxf(c[0] + b0, 0.f), fmaxf(c[1] + b1, 0.f))
                    : make_float2(0.f, 0.f);
                *(float2*)(T + rl1 * 256 + col) = v1
                    ? make_float2(fmaxf(c[2] + b0, 0.f), fmaxf(c[3] + b1, 0.f))
                    : make_float2(0.f, 0.f);
            }
        }
        __syncthreads();
        {
            int c = tid;
            int cur = segs[0];
            float sum = 0.f;
            for (int r = 0; r < TILE_M; r++) {
                int sg = segs[r];
                float v = T[r * 256 + c];
                if (sg != cur) {
                    atomicAdd(&out1[(size_t)cur * HDIM + c], sum);
                    sum = 0.f; cur = sg;
                }
                sum += v;
            }
            atomicAdd(&out1[(size_t)cur * HDIM + c], sum);
        }
        return;
    }

#pragma unroll
    for (int mi = 0; mi < 4; mi++) {
        int r0 = rowBlock + mi * 16 + (lane >> 2);
        int r1 = r0 + 8;
#pragma unroll
        for (int ni = 0; ni < 4; ni++) {
            int col = wn * 32 + ni * 8 + (lane & 3) * 2;
            float* c = acc[mi][ni];
            if (MODE == 0) {
                if (r0 < rowsM)
                    *(float2*)(out1 + (size_t)r0 * HDIM + col) = make_float2(c[0], c[1]);
                if (r1 < rowsM)
                    *(float2*)(out1 + (size_t)r1 * HDIM + col) = make_float2(c[2], c[3]);
            } else {
                if (r0 < rowsM)
                    *(float2*)(out1 + (size_t)r0 * HDIM + col) =
                        make_float2(fmaxf(c[0], 0.f), fmaxf(c[1], 0.f));
                if (r1 < rowsM)
                    *(float2*)(out1 + (size_t)r1 * HDIM + col) =
                        make_float2(fmaxf(c[2], 0.f), fmaxf(c[3], 0.f));
            }
        }
    }
}

// ---------------------------------------------------------------------------
// Pooling helpers
// ---------------------------------------------------------------------------
__global__ void zero_out_kernel(float* __restrict__ out)
{
    int i = blockIdx.x * blockDim.x + threadIdx.x;
    if (i < NMOLS * HDIM) out[i] = 0.f;
    if (i < NMOLS) g_counts[i] = 0.f;
}
__global__ void count_kernel(const int* __restrict__ scope)
{
    int i = blockIdx.x * blockDim.x + threadIdx.x;
    if (i < A_N) atomicAdd(&g_counts[__ldg(&scope[i])], 1.f);
}
__global__ void finalize_kernel(float* __restrict__ out)
{
    int i = blockIdx.x * blockDim.x + threadIdx.x;
    if (i >= NMOLS * HDIM) return;
    out[i] = out[i] / fmaxf(g_counts[i / HDIM], 1.f);
}

// ---------------------------------------------------------------------------
extern "C" void kernel_launch(void* const* d_in, const int* in_sizes, int n_in,
                              void* d_out, int out_size)
{
    const float* fatoms   = (const float*)d_in[0];
    const float* fbonds   = (const float*)d_in[1];
    const int*   agraph   = (const int*)  d_in[2];
    const int*   bgraph   = (const int*)  d_in[3];
    const float* tree_msg = (const float*)d_in[4];
    const int*   scope    = (const int*)  d_in[5];
    const float* W_i      = (const float*)d_in[6];
    const float* W_h      = (const float*)d_in[7];
    const float* W_o_w    = (const float*)d_in[8];
    const float* W_o_b    = (const float*)d_in[9];
    float* out = (float*)d_out;

    float *binput, *msg;
    __nv_bfloat16 *neihi, *neilo, *fbhi, *fblo, *fahi, *falo, *wthi, *wtlo;
    cudaGetSymbolAddress((void**)&binput, g_binput);
    cudaGetSymbolAddress((void**)&msg,    g_msg);
    cudaGetSymbolAddress((void**)&neihi,  g_neihi);
    cudaGetSymbolAddress((void**)&neilo,  g_neilo);
    cudaGetSymbolAddress((void**)&fbhi,   g_fbhi);
    cudaGetSymbolAddress((void**)&fblo,   g_fblo);
    cudaGetSymbolAddress((void**)&fahi,   g_fahi);
    cudaGetSymbolAddress((void**)&falo,   g_falo);
    cudaGetSymbolAddress((void**)&wthi,   g_WThi);
    cudaGetSymbolAddress((void**)&wtlo,   g_WTlo);

    cudaFuncSetAttribute(hgemm_kernel<0, 1>, cudaFuncAttributeMaxDynamicSharedMemorySize, HG_SMEM);
    cudaFuncSetAttribute(hgemm_kernel<1, 5>, cudaFuncAttributeMaxDynamicSharedMemorySize, HG_SMEM);
    cudaFuncSetAttribute(hgemm_kernel<2, 5>, cudaFuncAttributeMaxDynamicSharedMemorySize, HG_SMEM);

    const int gridB = (B_N + TILE_M - 1) / TILE_M;   // 3125
    const int gridA = (A_N + TILE_M - 1) / TILE_M;   // 1563
    dim3 gblk(64, 8);

    // 0) independent prep / pooling init up front
    zero_out_kernel<<<(NMOLS * HDIM + 255) / 256, 256>>>(out);
    count_kernel<<<(A_N + 255) / 256, 256>>>(scope);
    prep_a_kernel<<<(int)(((size_t)A_N * 16 + 255) / 256), 256>>>(fatoms, A_N, AFD, fahi, falo);

    // 1) prep fbonds split + W_i ; binput = fbonds @ W_i (pre-activation only)
    prep_a_kernel<<<(int)(((size_t)B_N * 16 + 255) / 256), 256>>>(fbonds, B_N, KI, fbhi, fblo);
    prep_w_cat_kernel<<<(256 * 64 + 255) / 256, 256>>>(W_i, KI, nullptr, 0, 64, wthi, wtlo);
    hgemm_kernel<0, 1><<<gridB, 256, HG_SMEM>>>(
        fbhi, fblo, 64, nullptr, nullptr, 0, wthi, wtlo, B_N,
        nullptr, nullptr, binput);

    // 2) two message-passing iterations with binput folded into K:
    //    msg = relu([nei | fbonds] @ [W_h ; W_i])
    prep_w_cat_kernel<<<(256 * 320 + 255) / 256, 256>>>(W_h, HDIM, W_i, KI, 320, wthi, wtlo);
    gather_split_kernel<1><<<(B_N + 7) / 8, gblk>>>(bgraph, B_N, tree_msg, binput, neihi, neilo);
    hgemm_kernel<1, 5><<<gridB, 256, HG_SMEM>>>(
        neihi, neilo, HDIM, fbhi, fblo, 64, wthi, wtlo, B_N,
        nullptr, nullptr, msg);
    gather_split_kernel<0><<<(B_N + 7) / 8, gblk>>>(bgraph, B_N, tree_msg, msg, neihi, neilo);
    hgemm_kernel<1, 5><<<gridB, 256, HG_SMEM>>>(
        neihi, neilo, HDIM, fbhi, fblo, 64, wthi, wtlo, B_N,
        nullptr, nullptr, msg);

    // 3) atom gather + output GEMM (run-length fused segment-sum)
    gather_split_kernel<0><<<(A_N + 7) / 8, gblk>>>(agraph, A_N, tree_msg, msg, neihi, neilo);
    prep_w_cat_kernel<<<(256 * 320 + 255) / 256, 256>>>(W_o_w + (size_t)AFD * 256, KO - AFD,
                                                        W_o_w, AFD, 320, wthi, wtlo);
    hgemm_kernel<2, 5><<<gridA, 256, HG_SMEM>>>(
        neihi, neilo, HDIM, fahi, falo, 64, wthi, wtlo, A_N,
        W_o_b, scope, out);
    finalize_kernel<<<(NMOLS * HDIM + 255) / 256, 256>>>(out);
}

// round 17
// speedup vs baseline: 1.1176x; 1.0120x over previous
#include <cuda_runtime.h>
#include <cuda_bf16.h>
#include <cstdint>

// Problem constants
#define A_N   100000
#define B_N   200000
#define M_N   20000
#define HDIM  256
#define MAXNB 10
#define NMOLS 2000
#define AFD   35
#define KI    40    // fbonds @ W_i
#define KO    291   // [fatoms, nei] @ W_o_w

// Scratch (device globals)
__device__ float g_binput[(size_t)B_N * HDIM];
__device__ float g_msg   [(size_t)B_N * HDIM];
__device__ float g_counts[NMOLS];
// Split bf16 operand buffers
__device__ __nv_bfloat16 g_neihi[(size_t)B_N * HDIM];
__device__ __nv_bfloat16 g_neilo[(size_t)B_N * HDIM];
__device__ __nv_bfloat16 g_fbhi [(size_t)B_N * 64];
__device__ __nv_bfloat16 g_fblo [(size_t)B_N * 64];
__device__ __nv_bfloat16 g_fahi [(size_t)A_N * 64];
__device__ __nv_bfloat16 g_falo [(size_t)A_N * 64];
// Pre-transposed, bf16-split weights: [N=256, KPAD<=320]
__device__ __nv_bfloat16 g_WThi[256 * 320];
__device__ __nv_bfloat16 g_WTlo[256 * 320];

// ---------------------------------------------------------------------------
// Helpers (base-sm_103-legal: ldmatrix / mma.sync / cp.async)
// ---------------------------------------------------------------------------
__device__ __forceinline__ uint32_t smem_u32(const void* p) {
    uint32_t a;
    asm("{ .reg .u64 t; cvta.to.shared.u64 t, %1; cvt.u32.u64 %0, t; }" : "=r"(a) : "l"(p));
    return a;
}
__device__ __forceinline__ void ldsm4(uint32_t* r, uint32_t addr) {
    asm volatile("ldmatrix.sync.aligned.m8n8.x4.shared.b16 {%0,%1,%2,%3}, [%4];"
                 : "=r"(r[0]), "=r"(r[1]), "=r"(r[2]), "=r"(r[3]) : "r"(addr));
}
__device__ __forceinline__ void mma_bf16(float* c, const uint32_t* a, uint32_t b0, uint32_t b1) {
    asm volatile("mma.sync.aligned.m16n8k16.row.col.f32.bf16.bf16.f32 "
                 "{%0,%1,%2,%3},{%4,%5,%6,%7},{%8,%9},{%0,%1,%2,%3};"
                 : "+f"(c[0]), "+f"(c[1]), "+f"(c[2]), "+f"(c[3])
                 : "r"(a[0]), "r"(a[1]), "r"(a[2]), "r"(a[3]), "r"(b0), "r"(b1));
}
__device__ __forceinline__ void cp_async16(uint32_t dst, const void* src) {
    asm volatile("cp.async.cg.shared.global [%0], [%1], 16;" :: "r"(dst), "l"(src));
}
__device__ __forceinline__ void cp_commit() {
    asm volatile("cp.async.commit_group;" ::: "memory");
}
template <int N>
__device__ __forceinline__ void cp_wait_group() {
    asm volatile("cp.async.wait_group %0;" :: "n"(N) : "memory");
}

#define SW128(o) ((o) ^ ((((uint32_t)(o)) >> 3) & 0x70))

__device__ __forceinline__ void split2(float v, unsigned short& h, unsigned short& l) {
    __nv_bfloat16 hb = __float2bfloat16_rn(v);
    float rem = v - __bfloat162float(hb);
    h = __bfloat16_as_ushort(hb);
    l = __bfloat16_as_ushort(__float2bfloat16_rn(rem));
}

// ---------------------------------------------------------------------------
// Gather + sum over MAX_NB neighbor rows of virtual concat [tree ; msg],
// emitting bf16 hi/lo split of the fp32 sum. RELU=1: apply relu to msg-branch
// rows on the fly.
// ---------------------------------------------------------------------------
template <int RELU>
__global__ void gather_split_kernel(const int* __restrict__ graph, int rows,
                                    const float* __restrict__ tree,
                                    const float* __restrict__ msg,
                                    __nv_bfloat16* __restrict__ outhi,
                                    __nv_bfloat16* __restrict__ outlo)
{
    int row = blockIdx.x * blockDim.y + threadIdx.y;
    if (row >= rows) return;
    int t = threadIdx.x;  // 0..63
    const int* gr = graph + (size_t)row * MAXNB;
    int idxs[MAXNB];
#pragma unroll
    for (int j = 0; j < MAXNB; j++) idxs[j] = __ldg(&gr[j]);

    const float4* srcs[MAXNB];
    bool im[MAXNB];
#pragma unroll
    for (int j = 0; j < MAXNB; j++) {
        im[j] = (idxs[j] >= M_N);
        srcs[j] = (const float4*)(im[j] ? (msg + (size_t)(idxs[j] - M_N) * HDIM)
                                        : (tree + (size_t)idxs[j] * HDIM)) + t;
    }
    float4 acc0 = make_float4(0.f, 0.f, 0.f, 0.f);
    float4 acc1 = make_float4(0.f, 0.f, 0.f, 0.f);
#pragma unroll
    for (int j = 0; j < MAXNB; j += 2) {
        float4 v0 = __ldg(srcs[j]);
        float4 v1 = __ldg(srcs[j + 1]);
        if (RELU && im[j]) {
            v0.x = fmaxf(v0.x, 0.f); v0.y = fmaxf(v0.y, 0.f);
            v0.z = fmaxf(v0.z, 0.f); v0.w = fmaxf(v0.w, 0.f);
        }
        if (RELU && im[j + 1]) {
            v1.x = fmaxf(v1.x, 0.f); v1.y = fmaxf(v1.y, 0.f);
            v1.z = fmaxf(v1.z, 0.f); v1.w = fmaxf(v1.w, 0.f);
        }
        acc0.x += v0.x; acc0.y += v0.y; acc0.z += v0.z; acc0.w += v0.w;
        acc1.x += v1.x; acc1.y += v1.y; acc1.z += v1.z; acc1.w += v1.w;
    }
    float4 acc = make_float4(acc0.x + acc1.x, acc0.y + acc1.y,
                             acc0.z + acc1.z, acc0.w + acc1.w);
    unsigned short h0,h1,h2,h3,l0,l1,l2,l3;
    split2(acc.x,h0,l0); split2(acc.y,h1,l1); split2(acc.z,h2,l2); split2(acc.w,h3,l3);
    uint2 uh, ul;
    uh.x = (uint32_t)h0 | ((uint32_t)h1 << 16);
    uh.y = (uint32_t)h2 | ((uint32_t)h3 << 16);
    ul.x = (uint32_t)l0 | ((uint32_t)l1 << 16);
    ul.y = (uint32_t)l2 | ((uint32_t)l3 << 16);
    ((uint2*)outhi)[(size_t)row * 64 + t] = uh;
    ((uint2*)outlo)[(size_t)row * 64 + t] = ul;
}

// ---------------------------------------------------------------------------
// Vectorized prep: fp32 [rows, inK] -> bf16 hi/lo [rows, 64] zero-padded.
// float4 fast path only when 16B-aligned (inK % 4 == 0 and in-bounds).
// ---------------------------------------------------------------------------
__global__ void prep_a_kernel(const float* __restrict__ in, int rows, int inK,
                              __nv_bfloat16* __restrict__ hi, __nv_bfloat16* __restrict__ lo)
{
    size_t idx = (size_t)blockIdx.x * blockDim.x + threadIdx.x;   // r*16 + kq
    if (idx >= (size_t)rows * 16) return;
    int r  = (int)(idx >> 4);
    int gc = (int)(idx & 15) * 4;
    float4 v;
    if ((inK & 3) == 0 && gc + 3 < inK) {
        v = __ldg((const float4*)(in + (size_t)r * inK + gc));
    } else {
        const float* rp = in + (size_t)r * inK;
        v.x = (gc + 0 < inK) ? __ldg(rp + gc + 0) : 0.f;
        v.y = (gc + 1 < inK) ? __ldg(rp + gc + 1) : 0.f;
        v.z = (gc + 2 < inK) ? __ldg(rp + gc + 2) : 0.f;
        v.w = (gc + 3 < inK) ? __ldg(rp + gc + 3) : 0.f;
    }
    unsigned short h0,h1,h2,h3,l0,l1,l2,l3;
    split2(v.x,h0,l0); split2(v.y,h1,l1); split2(v.z,h2,l2); split2(v.w,h3,l3);
    uint2 uh, ul;
    uh.x = (uint32_t)h0 | ((uint32_t)h1 << 16);
    uh.y = (uint32_t)h2 | ((uint32_t)h3 << 16);
    ul.x = (uint32_t)l0 | ((uint32_t)l1 << 16);
    ul.y = (uint32_t)l2 | ((uint32_t)l3 << 16);
    ((uint2*)hi)[idx] = uh;
    ((uint2*)lo)[idx] = ul;
}

// ---------------------------------------------------------------------------
// Weight prep (concat): WT hi/lo [256, Kpad] from two stacked fp32 sources
// ---------------------------------------------------------------------------
__global__ void prep_w_cat_kernel(const float* __restrict__ W1, int K1,
                                  const float* __restrict__ W2, int K2,
                                  int Kpad,
                                  __nv_bfloat16* __restrict__ hi,
                                  __nv_bfloat16* __restrict__ lo)
{
    int i = blockIdx.x * blockDim.x + threadIdx.x;
    if (i >= 256 * Kpad) return;
    int n = i / Kpad, k = i % Kpad;
    float v = 0.f;
    if (k < K1)            v = __ldg(&W1[(size_t)k * 256 + n]);
    else if (k < K1 + K2)  v = __ldg(&W2[(size_t)(k - K1) * 256 + n]);
    unsigned short h, l; split2(v, h, l);
    hi[i] = __ushort_as_bfloat16(h);
    lo[i] = __ushort_as_bfloat16(l);
}

// ---------------------------------------------------------------------------
// bf16 3-split HGEMM with split-B software pipelining (R15 schedule) plus
// zero-K trimming: the last stage's live K is only 40 (fbonds) / 35 (fatoms)
// of 64, so kk=3 (cols 48..63, all zero-padded) is skipped in both passes.
// 64x256 CTA tile, 256 threads (8 warps, 1x8), 64x32 warp tiles, K-stage 64.
// smem: A double (2x16KB) + B_hi (32KB) + B_lo (32KB) = 96KB -> 2 CTAs/SM.
// MODE 0: A = fbonds           -> out1 = C (binput pre-activation)
// MODE 1: A = [nei | fbonds]   -> out1 = relu(C)
// MODE 2: A = [nei | fatoms]   -> run-length segment reduction over the
//         sorted scope (smem staging in dead B buffers), ~2 atomics/col/CTA.
// ---------------------------------------------------------------------------
#define TILE_M   64
#define ABUF(s)  ((uint32_t)((s) & 1) * 16384)
#define A_LO_OFF 8192
#define B_HI     32768
#define B_LO     65536
#define HG_SMEM  98304

template <int MODE, int NS>
__global__ __launch_bounds__(256, 2)
void hgemm_kernel(const __nv_bfloat16* __restrict__ Ahi,
                  const __nv_bfloat16* __restrict__ Alo,
                  int strideA,
                  const __nv_bfloat16* __restrict__ A2hi,
                  const __nv_bfloat16* __restrict__ A2lo,
                  int strideA2,
                  const __nv_bfloat16* __restrict__ WThi,
                  const __nv_bfloat16* __restrict__ WTlo,
                  int rowsM,
                  const float* __restrict__ bias,
                  const int*   __restrict__ scope,
                  float* __restrict__ out1)
{
    constexpr int KPAD = NS * 64;
    extern __shared__ char smem[];
    const uint32_t sb = smem_u32(smem);
    const int tid  = threadIdx.x;
    const int lane = tid & 31;
    const int wn   = tid >> 5;                 // 1 x 8 warp grid
    const int rowBlock = blockIdx.x * TILE_M;

    // ldmatrix lane-address components
    const int arow  = ((lane >> 3) & 1) * 8 + (lane & 7);
    const int akb   = (lane >> 4) * 16;
    const int bnrow = ((lane >> 4) & 1) * 8 + (lane & 7);
    const int bkb   = ((lane >> 3) & 1) * 16;

    float acc[4][4][4];   // [mi][ni(8cols)][quad]
#pragma unroll
    for (int mi = 0; mi < 4; mi++)
#pragma unroll
        for (int ni = 0; ni < 4; ni++)
#pragma unroll
            for (int e = 0; e < 4; e++) acc[mi][ni][e] = 0.f;

    auto cpA = [&](int s) {   // 64 rows x 64 K bf16 (hi+lo), SW128
        const __nv_bfloat16 *sh, *sl;
        int stride, kk0;
        if (MODE != 0 && s == NS - 1) { sh = A2hi; sl = A2lo; stride = strideA2; kk0 = 0; }
        else                          { sh = Ahi;  sl = Alo;  stride = strideA;  kk0 = s * 64; }
        uint32_t abuf = ABUF(s);
#pragma unroll
        for (int i = 0; i < 2; i++) {
            int idx = i * 256 + tid;
            int r = idx >> 3, c = idx & 7;
            int grow = rowBlock + r;
            if (grow >= rowsM) grow = rowsM - 1;   // clamp; epilogue guards
            uint32_t dsw = SW128(r * 128 + c * 16);
            size_t src = (size_t)grow * stride + kk0 + c * 8;
            cp_async16(sb + abuf + dsw,            sh + src);
            cp_async16(sb + abuf + A_LO_OFF + dsw, sl + src);
        }
    };

    auto cpBhalf = [&](int s, uint32_t dstOff, const __nv_bfloat16* WT) {
        int k0 = s * 64;
#pragma unroll
        for (int i = 0; i < 8; i++) {
            int idx = i * 256 + tid;
            int n = idx >> 3, c = idx & 7;
            uint32_t dsw = SW128(n * 128 + c * 16);
            cp_async16(sb + dstOff + dsw, WT + (size_t)n * KPAD + k0 + c * 8);
        }
    };

    // Prologue: A(0), Bhi(0), Blo(0) as three groups
    cpA(0);                    cp_commit();
    cpBhalf(0, B_HI, WThi);    cp_commit();
    cpBhalf(0, B_LO, WTlo);    cp_commit();

    for (int s = 0; s < NS; s++) {
        const uint32_t aBase = sb + ABUF(s);
        // Live kk count this stage: last stage has <=48 live K cols
        // (fbonds KI=40 / fatoms AFD=35 / GEMM0 KI=40) -> skip all-zero kk=3.
        const int kkmax = (s == NS - 1) ? 3 : 4;
        cp_wait_group<1>();        // A(s) + Bhi(s) resident; Blo(s) may fly
        __syncthreads();

        // ---- hi-B pass: (ahi + alo) x Bhi ----
        for (int kk = 0; kk < kkmax; kk++) {
            uint32_t bsw0 = SW128((uint32_t)(wn * 32 + bnrow) * 128 + kk * 32 + bkb);
            uint32_t bsw1 = SW128((uint32_t)(wn * 32 + 16 + bnrow) * 128 + kk * 32 + bkb);
            uint32_t b0[4], b1[4];
            ldsm4(b0, sb + B_HI + bsw0);
            ldsm4(b1, sb + B_HI + bsw1);
#pragma unroll
            for (int mi = 0; mi < 4; mi++) {
                uint32_t asw = SW128((uint32_t)(mi * 16 + arow) * 128 + kk * 32 + akb);
                uint32_t ahi[4], alo[4];
                ldsm4(ahi, aBase + asw);
                ldsm4(alo, aBase + A_LO_OFF + asw);
                mma_bf16(acc[mi][0], ahi, b0[0], b0[1]);
                mma_bf16(acc[mi][1], ahi, b0[2], b0[3]);
                mma_bf16(acc[mi][0], alo, b0[0], b0[1]);
                mma_bf16(acc[mi][1], alo, b0[2], b0[3]);
                mma_bf16(acc[mi][2], ahi, b1[0], b1[1]);
                mma_bf16(acc[mi][3], ahi, b1[2], b1[3]);
                mma_bf16(acc[mi][2], alo, b1[0], b1[1]);
                mma_bf16(acc[mi][3], alo, b1[2], b1[3]);
            }
        }
        __syncthreads();           // Bhi buffer free

        if (s + 1 < NS) {          // stream A(s+1)+Bhi(s+1) under the lo-pass
            cpA(s + 1);
            cpBhalf(s + 1, B_HI, WThi);
            cp_commit();
            cp_wait_group<1>();    // Blo(s) done
        } else {
            cp_wait_group<0>();
        }
        __syncthreads();

        // ---- lo-B pass: ahi x Blo ----
        for (int kk = 0; kk < kkmax; kk++) {
            uint32_t bsw0 = SW128((uint32_t)(wn * 32 + bnrow) * 128 + kk * 32 + bkb);
            uint32_t bsw1 = SW128((uint32_t)(wn * 32 + 16 + bnrow) * 128 + kk * 32 + bkb);
            uint32_t b0[4], b1[4];
            ldsm4(b0, sb + B_LO + bsw0);
            ldsm4(b1, sb + B_LO + bsw1);
#pragma unroll
            for (int mi = 0; mi < 4; mi++) {
                uint32_t asw = SW128((uint32_t)(mi * 16 + arow) * 128 + kk * 32 + akb);
                uint32_t ahi[4];
                ldsm4(ahi, aBase + asw);
                mma_bf16(acc[mi][0], ahi, b0[0], b0[1]);
                mma_bf16(acc[mi][1], ahi, b0[2], b0[3]);
                mma_bf16(acc[mi][2], ahi, b1[0], b1[1]);
                mma_bf16(acc[mi][3], ahi, b1[2], b1[3]);
            }
        }
        __syncthreads();           // Blo buffer free

        if (s + 1 < NS) {
            cpBhalf(s + 1, B_LO, WTlo);
            cp_commit();
        }
    }

    // ---- Epilogue ----
    if (MODE == 2) {
        // Stage relu(C + bias) into dead B smem as T[64][256], then run-length
        // reduce along sorted scope -> ~2 atomics/col/CTA.
        float* T    = (float*)(smem + B_HI);   // 64KB: B_HI..end
        int*   segs = (int*)(smem);            // 256B in dead A buffer
        if (tid < TILE_M) {
            int gr = rowBlock + tid;
            if (gr >= rowsM) gr = rowsM - 1;
            segs[tid] = __ldg(&scope[gr]);
        }
#pragma unroll
        for (int mi = 0; mi < 4; mi++) {
            int rl0 = mi * 16 + (lane >> 2);
            int rl1 = rl0 + 8;
            bool v0 = (rowBlock + rl0 < rowsM);
            bool v1 = (rowBlock + rl1 < rowsM);
#pragma unroll
            for (int ni = 0; ni < 4; ni++) {
                int col = wn * 32 + ni * 8 + (lane & 3) * 2;
                float b0 = __ldg(&bias[col]), b1 = __ldg(&bias[col + 1]);
                float* c = acc[mi][ni];
                *(float2*)(T + rl0 * 256 + col) = v0
                    ? make_float2(fmaxf(c[0] + b0, 0.f), fmaxf(c[1] + b1, 0.f))
                    : make_float2(0.f, 0.f);
                *(float2*)(T + rl1 * 256 + col) = v1
                    ? make_float2(fmaxf(c[2] + b0, 0.f), fmaxf(c[3] + b1, 0.f))
                    : make_float2(0.f, 0.f);
            }
        }
        __syncthreads();
        {
            int c = tid;
            int cur = segs[0];
            float sum = 0.f;
            for (int r = 0; r < TILE_M; r++) {
                int sg = segs[r];
                float v = T[r * 256 + c];
                if (sg != cur) {
                    atomicAdd(&out1[(size_t)cur * HDIM + c], sum);
                    sum = 0.f; cur = sg;
                }
                sum += v;
            }
            atomicAdd(&out1[(size_t)cur * HDIM + c], sum);
        }
        return;
    }

#pragma unroll
    for (int mi = 0; mi < 4; mi++) {
        int r0 = rowBlock + mi * 16 + (lane >> 2);
        int r1 = r0 + 8;
#pragma unroll
        for (int ni = 0; ni < 4; ni++) {
            int col = wn * 32 + ni * 8 + (lane & 3) * 2;
            float* c = acc[mi][ni];
            if (MODE == 0) {
                if (r0 < rowsM)
                    *(float2*)(out1 + (size_t)r0 * HDIM + col) = make_float2(c[0], c[1]);
                if (r1 < rowsM)
                    *(float2*)(out1 + (size_t)r1 * HDIM + col) = make_float2(c[2], c[3]);
            } else {
                if (r0 < rowsM)
                    *(float2*)(out1 + (size_t)r0 * HDIM + col) =
                        make_float2(fmaxf(c[0], 0.f), fmaxf(c[1], 0.f));
                if (r1 < rowsM)
                    *(float2*)(out1 + (size_t)r1 * HDIM + col) =
                        make_float2(fmaxf(c[2], 0.f), fmaxf(c[3], 0.f));
            }
        }
    }
}

// ---------------------------------------------------------------------------
// Pooling helpers
// ---------------------------------------------------------------------------
__global__ void zero_out_kernel(float* __restrict__ out)
{
    int i = blockIdx.x * blockDim.x + threadIdx.x;
    if (i < NMOLS * HDIM) out[i] = 0.f;
    if (i < NMOLS) g_counts[i] = 0.f;
}
__global__ void count_kernel(const int* __restrict__ scope)
{
    int i = blockIdx.x * blockDim.x + threadIdx.x;
    if (i < A_N) atomicAdd(&g_counts[__ldg(&scope[i])], 1.f);
}
__global__ void finalize_kernel(float* __restrict__ out)
{
    int i = blockIdx.x * blockDim.x + threadIdx.x;
    if (i >= NMOLS * HDIM) return;
    out[i] = out[i] / fmaxf(g_counts[i / HDIM], 1.f);
}

// ---------------------------------------------------------------------------
extern "C" void kernel_launch(void* const* d_in, const int* in_sizes, int n_in,
                              void* d_out, int out_size)
{
    const float* fatoms   = (const float*)d_in[0];
    const float* fbonds   = (const float*)d_in[1];
    const int*   agraph   = (const int*)  d_in[2];
    const int*   bgraph   = (const int*)  d_in[3];
    const float* tree_msg = (const float*)d_in[4];
    const int*   scope    = (const int*)  d_in[5];
    const float* W_i      = (const float*)d_in[6];
    const float* W_h      = (const float*)d_in[7];
    const float* W_o_w    = (const float*)d_in[8];
    const float* W_o_b    = (const float*)d_in[9];
    float* out = (float*)d_out;

    float *binput, *msg;
    __nv_bfloat16 *neihi, *neilo, *fbhi, *fblo, *fahi, *falo, *wthi, *wtlo;
    cudaGetSymbolAddress((void**)&binput, g_binput);
    cudaGetSymbolAddress((void**)&msg,    g_msg);
    cudaGetSymbolAddress((void**)&neihi,  g_neihi);
    cudaGetSymbolAddress((void**)&neilo,  g_neilo);
    cudaGetSymbolAddress((void**)&fbhi,   g_fbhi);
    cudaGetSymbolAddress((void**)&fblo,   g_fblo);
    cudaGetSymbolAddress((void**)&fahi,   g_fahi);
    cudaGetSymbolAddress((void**)&falo,   g_falo);
    cudaGetSymbolAddress((void**)&wthi,   g_WThi);
    cudaGetSymbolAddress((void**)&wtlo,   g_WTlo);

    cudaFuncSetAttribute(hgemm_kernel<0, 1>, cudaFuncAttributeMaxDynamicSharedMemorySize, HG_SMEM);
    cudaFuncSetAttribute(hgemm_kernel<1, 5>, cudaFuncAttributeMaxDynamicSharedMemorySize, HG_SMEM);
    cudaFuncSetAttribute(hgemm_kernel<2, 5>, cudaFuncAttributeMaxDynamicSharedMemorySize, HG_SMEM);

    const int gridB = (B_N + TILE_M - 1) / TILE_M;   // 3125
    const int gridA = (A_N + TILE_M - 1) / TILE_M;   // 1563
    dim3 gblk(64, 8);

    // 0) independent prep / pooling init up front
    zero_out_kernel<<<(NMOLS * HDIM + 255) / 256, 256>>>(out);
    count_kernel<<<(A_N + 255) / 256, 256>>>(scope);
    prep_a_kernel<<<(int)(((size_t)A_N * 16 + 255) / 256), 256>>>(fatoms, A_N, AFD, fahi, falo);

    // 1) prep fbonds split + W_i ; binput = fbonds @ W_i (pre-activation only)
    prep_a_kernel<<<(int)(((size_t)B_N * 16 + 255) / 256), 256>>>(fbonds, B_N, KI, fbhi, fblo);
    prep_w_cat_kernel<<<(256 * 64 + 255) / 256, 256>>>(W_i, KI, nullptr, 0, 64, wthi, wtlo);
    hgemm_kernel<0, 1><<<gridB, 256, HG_SMEM>>>(
        fbhi, fblo, 64, nullptr, nullptr, 0, wthi, wtlo, B_N,
        nullptr, nullptr, binput);

    // 2) two message-passing iterations with binput folded into K:
    //    msg = relu([nei | fbonds] @ [W_h ; W_i])
    prep_w_cat_kernel<<<(256 * 320 + 255) / 256, 256>>>(W_h, HDIM, W_i, KI, 320, wthi, wtlo);
    gather_split_kernel<1><<<(B_N + 7) / 8, gblk>>>(bgraph, B_N, tree_msg, binput, neihi, neilo);
    hgemm_kernel<1, 5><<<gridB, 256, HG_SMEM>>>(
        neihi, neilo, HDIM, fbhi, fblo, 64, wthi, wtlo, B_N,
        nullptr, nullptr, msg);
    gather_split_kernel<0><<<(B_N + 7) / 8, gblk>>>(bgraph, B_N, tree_msg, msg, neihi, neilo);
    hgemm_kernel<1, 5><<<gridB, 256, HG_SMEM>>>(
        neihi, neilo, HDIM, fbhi, fblo, 64, wthi, wtlo, B_N,
        nullptr, nullptr, msg);

    // 3) atom gather + output GEMM (run-length fused segment-sum)
    gather_split_kernel<0><<<(A_N + 7) / 8, gblk>>>(agraph, A_N, tree_msg, msg, neihi, neilo);
    prep_w_cat_kernel<<<(256 * 320 + 255) / 256, 256>>>(W_o_w + (size_t)AFD * 256, KO - AFD,
                                                        W_o_w, AFD, 320, wthi, wtlo);
    hgemm_kernel<2, 5><<<gridA, 256, HG_SMEM>>>(
        neihi, neilo, HDIM, fahi, falo, 64, wthi, wtlo, A_N,
        W_o_b, scope, out);
    finalize_kernel<<<(NMOLS * HDIM + 255) / 256, 256>>>(out);
}